// round 11
// baseline (speedup 1.0000x reference)
#include <cuda_runtime.h>
#include <cuda_bf16.h>
#include <cstdint>

// Problem constants
#define Bb 16
#define NK 2048
#define TK 4096
#define Hh 256

// -------------------- scratch (device globals; no allocation) --------------------
__device__ __align__(16) float          g_dec[Bb * Hh];          // dec_fea (16,256)
__device__ __align__(16) __nv_bfloat16  g_wt[Hh * Hh];           // enc_proj^T in bf16, [n][k]
__device__ __align__(16) float          g_scores[Bb * NK];       // attention scores
__device__ __align__(16) float          g_ctp[8 * Bb * Hh];      // c_t partials (8 k-chunks)
__device__ __align__(16) float          g_tokp[8 * Bb * TK];     // tok partials (8 k-chunks)
__device__ __align__(16) float          g_onehp[16 * Bb * NK];   // one_hop partials (16 k-chunks)
__device__ __align__(16) float          g_twohp[64 * Bb * NK];   // two_hop partials (64 k-chunks)

// -------------------- K1: W transpose->bf16  +  dec_fea --------------------------
__global__ void __launch_bounds__(256) prep_kernel(const float* __restrict__ encw,
                                                   const float* __restrict__ s_t,
                                                   const float* __restrict__ decw,
                                                   const float* __restrict__ bias) {
    if (blockIdx.x < 64) {
        __shared__ float tile[32][33];
        const int bx = blockIdx.x & 7;        // k tile
        const int by = blockIdx.x >> 3;       // n tile
        const int k0 = bx * 32, n0 = by * 32;
        const int tx = threadIdx.x & 31, ty = threadIdx.x >> 5;
#pragma unroll
        for (int i = 0; i < 32; i += 8)
            tile[ty + i][tx] = encw[(k0 + ty + i) * 256 + n0 + tx];
        __syncthreads();
#pragma unroll
        for (int i = 0; i < 32; i += 8)
            g_wt[(n0 + ty + i) * 256 + k0 + tx] = __float2bfloat16(tile[tx][ty + i]);
    } else {
        const int b = blockIdx.x - 64;
        const int h = threadIdx.x;
        __shared__ float ss[512];
        for (int i = threadIdx.x; i < 512; i += 256) ss[i] = s_t[b * 512 + i];
        __syncthreads();
        float acc = bias[h];
#pragma unroll 8
        for (int j = 0; j < 512; j++) acc += ss[j] * decw[j * 256 + h];
        g_dec[b * 256 + h] = acc;
    }
}

// -------------------- K2: persistent scores GEMM, A register-prefetch pipeline -----
// (R4 design: measured 32.4us, the best of three GEMM variants tried)
#define GEMM_SMEM (256 * 264 * 2 + 64 * 264 * 2 + 64 * 8 * 4 + 256 * 4)

#define LDSM4(r0, r1, r2, r3, addr)                                              \
    asm volatile("ldmatrix.sync.aligned.m8n8.x4.shared.b16 {%0,%1,%2,%3}, [%4];" \
                 : "=r"(r0), "=r"(r1), "=r"(r2), "=r"(r3)                        \
                 : "r"(addr))

#define MMA16816(c, a, b0v, b1v)                                                   \
    asm volatile(                                                                  \
        "mma.sync.aligned.m16n8k16.row.col.f32.bf16.bf16.f32 "                     \
        "{%0,%1,%2,%3},{%4,%5,%6,%7},{%8,%9},{%0,%1,%2,%3};"                       \
        : "+f"(c[0]), "+f"(c[1]), "+f"(c[2]), "+f"(c[3])                           \
        : "r"(a[0]), "r"(a[1]), "r"(a[2]), "r"(a[3]), "r"(b0v), "r"(b1v))

__global__ void __launch_bounds__(256) gemm_scores_kernel(const float* __restrict__ enc,
                                                          const float* __restrict__ vw) {
    extern __shared__ char smraw[];
    __nv_bfloat16* Ws = reinterpret_cast<__nv_bfloat16*>(smraw);   // [256][264]
    __nv_bfloat16* As = Ws + 256 * 264;                            // [64][264]
    float* sred = reinterpret_cast<float*>(As + 64 * 264);         // [64][8]
    float* vs = sred + 64 * 8;                                     // [256]

    const int tid = threadIdx.x;
    const int warp = tid >> 5;
    const int lane = tid & 31;

    {
        const uint4* src = reinterpret_cast<const uint4*>(g_wt);
        for (int i = tid; i < 8192; i += 256) {
            const int n = i >> 5, c = i & 31;
            *reinterpret_cast<uint4*>(Ws + n * 264 + c * 8) = src[i];
        }
    }
    if (tid < 256) vs[tid] = vw[tid];

    const unsigned AsB = (unsigned)__cvta_generic_to_shared(As);
    const unsigned WsB = (unsigned)__cvta_generic_to_shared(Ws);
    const int n0w = warp * 32;

    unsigned a_off[4], b_off[2];
#pragma unroll
    for (int mt = 0; mt < 4; mt++)
        a_off[mt] = AsB + 2u * ((unsigned)((mt * 16 + (lane & 15)) * 264 + ((lane >> 4) << 3)));
#pragma unroll
    for (int nt2 = 0; nt2 < 2; nt2++)
        b_off[nt2] = WsB + 2u * ((unsigned)((n0w + nt2 * 16 + ((lane >> 4) << 3) + (lane & 7)) * 264 +
                                            (((lane >> 3) & 1) << 3)));

    const float4* srcBase = reinterpret_cast<const float4*>(enc);

    float4 pf[16];
    int t = blockIdx.x;
    if (t < 512) {
        const float4* s = srcBase + (size_t)t * 4096;
#pragma unroll
        for (int j = 0; j < 16; j++) pf[j] = s[tid + j * 256];
    }

    for (; t < 512; t += gridDim.x) {
        const int m0 = t * 64;
        __syncthreads();
#pragma unroll
        for (int j = 0; j < 16; j++) {
            const int i = tid + j * 256;
            const int r = i >> 6, c = i & 63;
            __nv_bfloat162 p0 = __floats2bfloat162_rn(pf[j].x, pf[j].y);
            __nv_bfloat162 p1 = __floats2bfloat162_rn(pf[j].z, pf[j].w);
            uint2 u;
            u.x = *reinterpret_cast<const unsigned*>(&p0);
            u.y = *reinterpret_cast<const unsigned*>(&p1);
            *reinterpret_cast<uint2*>(As + r * 264 + c * 4) = u;
        }
        const int tn = t + gridDim.x;
        if (tn < 512) {
            const float4* s = srcBase + (size_t)tn * 4096;
#pragma unroll
            for (int j = 0; j < 16; j++) pf[j] = s[tid + j * 256];
        }
        __syncthreads();

        float acc[4][4][4];
#pragma unroll
        for (int mt = 0; mt < 4; mt++)
#pragma unroll
            for (int nt = 0; nt < 4; nt++)
#pragma unroll
                for (int i = 0; i < 4; i++) acc[mt][nt][i] = 0.0f;

#pragma unroll
        for (int ks = 0; ks < 16; ks++) {
            const unsigned k0b = 2u * (unsigned)(ks * 16);
            unsigned a[4][4];
            unsigned bq[4][2];
#pragma unroll
            for (int mt = 0; mt < 4; mt++)
                LDSM4(a[mt][0], a[mt][1], a[mt][2], a[mt][3], a_off[mt] + k0b);
#pragma unroll
            for (int nt2 = 0; nt2 < 2; nt2++) {
                unsigned r0, r1, r2, r3;
                LDSM4(r0, r1, r2, r3, b_off[nt2] + k0b);
                bq[nt2 * 2][0] = r0;     bq[nt2 * 2][1] = r1;
                bq[nt2 * 2 + 1][0] = r2; bq[nt2 * 2 + 1][1] = r3;
            }
#pragma unroll
            for (int mt = 0; mt < 4; mt++)
#pragma unroll
                for (int nt = 0; nt < 4; nt++)
                    MMA16816(acc[mt][nt], a[mt], bq[nt][0], bq[nt][1]);
        }

        const int b = m0 >> 11;
        const float* dec = g_dec + b * 256;
        float decv[8], vv[8];
#pragma unroll
        for (int nt = 0; nt < 4; nt++)
#pragma unroll
            for (int q = 0; q < 2; q++) {
                const int col = n0w + nt * 8 + ((lane & 3) << 1) + q;
                decv[nt * 2 + q] = dec[col];
                vv[nt * 2 + q] = vs[col];
            }
        float rs[4][2] = {{0.f, 0.f}, {0.f, 0.f}, {0.f, 0.f}, {0.f, 0.f}};
#pragma unroll
        for (int mt = 0; mt < 4; mt++)
#pragma unroll
            for (int nt = 0; nt < 4; nt++)
#pragma unroll
                for (int i = 0; i < 4; i++) {
                    const float f = acc[mt][nt][i] + decv[nt * 2 + (i & 1)];
                    rs[mt][i >> 1] += tanhf(f) * vv[nt * 2 + (i & 1)];
                }
#pragma unroll
        for (int mt = 0; mt < 4; mt++)
#pragma unroll
            for (int j = 0; j < 2; j++) {
                float v = rs[mt][j];
                v += __shfl_xor_sync(0xffffffffu, v, 1);
                v += __shfl_xor_sync(0xffffffffu, v, 2);
                if ((lane & 3) == 0)
                    sred[(mt * 16 + (lane >> 2) + j * 8) * 8 + warp] = v;
            }
        __syncthreads();
        if (tid < 64) {
            float s = 0.f;
#pragma unroll
            for (int w = 0; w < 8; w++) s += sred[tid * 8 + w];
            g_scores[m0 + tid] = s;
        }
    }
}

// -------------------- block-wide masked softmax into SMEM (deterministic) ----------
__device__ __forceinline__ void block_softmax(int b, const float* __restrict__ mask,
                                              float* attnAll, float* wred) {
    const int tid = threadIdx.x;
    const int lane = tid & 31, wid = tid >> 5;
    const float* sc = g_scores + b * 2048;
    const float* mk = mask + b * 2048;
    float v[8], m[8];
    float lmax = -1e30f;
#pragma unroll
    for (int i = 0; i < 8; i++) {
        v[i] = sc[tid + i * 256];
        m[i] = mk[tid + i * 256];
        lmax = fmaxf(lmax, v[i]);
    }
#pragma unroll
    for (int o = 16; o > 0; o >>= 1) lmax = fmaxf(lmax, __shfl_xor_sync(0xffffffffu, lmax, o));
    if (lane == 0) wred[wid] = lmax;
    __syncthreads();
    float gmax = wred[0];
#pragma unroll
    for (int w = 1; w < 8; w++) gmax = fmaxf(gmax, wred[w]);
    __syncthreads();
    float lsum = 0.f;
#pragma unroll
    for (int i = 0; i < 8; i++) {
        v[i] = expf(v[i] - gmax) * m[i];
        lsum += v[i];
    }
#pragma unroll
    for (int o = 16; o > 0; o >>= 1) lsum += __shfl_xor_sync(0xffffffffu, lsum, o);
    if (lane == 0) wred[wid] = lsum;
    __syncthreads();
    float gsum = 0.f;
#pragma unroll
    for (int w = 0; w < 8; w++) gsum += wred[w];
    const float inv = 1.0f / gsum;
#pragma unroll
    for (int i = 0; i < 8; i++) attnAll[tid + i * 256] = v[i] * inv;
    __syncthreads();
}

// -------------------- K3: fused streamer: softmax + tokp + ct + onehp --------------
// blocks [0,512):    tokp   (n2t, __ldcs); tc==0 blocks write attn_out
// blocks [512,640):  ct     (enc, partly L2-hot from gemm)
// blocks [640,1152): onehp  (graph)
__global__ void __launch_bounds__(256) stream_kernel(const float* __restrict__ n2t,
                                                     const float* __restrict__ enc,
                                                     const float* __restrict__ graph,
                                                     const float* __restrict__ mask,
                                                     float* __restrict__ attn_out) {
    const int bid = blockIdx.x;
    const int tid = threadIdx.x;
    __shared__ float attnAll[2048];
    __shared__ float wred[8];
    __shared__ float4 red[256];

    if (bid < 512) {
        const int b = bid >> 5;
        const int tc = (bid >> 3) & 3;
        const int kc = bid & 7;
        block_softmax(b, mask, attnAll, wred);
        if (tc == 0) attn_out[b * 2048 + kc * 256 + tid] = attnAll[kc * 256 + tid];
        const float* asm_ = attnAll + kc * 256;
        const float4* N4 = reinterpret_cast<const float4*>(n2t) +
                           (size_t)b * 2048 * 1024 + (size_t)kc * 256 * 1024 + tc * 256 + tid;
        float4 acc = make_float4(0.f, 0.f, 0.f, 0.f);
#pragma unroll 8
        for (int k = 0; k < 256; k++) {
            const float a = asm_[k];
            const float4 v = __ldcs(&N4[(size_t)k * 1024]);
            acc.x += a * v.x; acc.y += a * v.y; acc.z += a * v.z; acc.w += a * v.w;
        }
        reinterpret_cast<float4*>(g_tokp)[(kc * 16 + b) * 1024 + tc * 256 + tid] = acc;
    } else if (bid < 640) {
        const int idx = bid - 512;
        const int b = idx >> 3, kc = idx & 7;
        const int rg = tid >> 6;
        const int hc = tid & 63;
        block_softmax(b, mask, attnAll, wred);
        const float* asm_ = attnAll + kc * 256;
        const float4* E4 = reinterpret_cast<const float4*>(enc) +
                           (size_t)(b * 2048 + kc * 256) * 64 + hc;
        float4 acc = make_float4(0.f, 0.f, 0.f, 0.f);
#pragma unroll 8
        for (int k = rg; k < 256; k += 4) {
            const float a = asm_[k];
            const float4 e = E4[(size_t)k * 64];
            acc.x += a * e.x; acc.y += a * e.y; acc.z += a * e.z; acc.w += a * e.w;
        }
        red[tid] = acc;
        __syncthreads();
        if (tid < 64) {
            float4 s0 = red[tid], s1 = red[tid + 64], s2 = red[tid + 128], s3 = red[tid + 192];
            float4 s;
            s.x = (s0.x + s1.x) + (s2.x + s3.x);
            s.y = (s0.y + s1.y) + (s2.y + s3.y);
            s.z = (s0.z + s1.z) + (s2.z + s3.z);
            s.w = (s0.w + s1.w) + (s2.w + s3.w);
            reinterpret_cast<float4*>(g_ctp)[(kc * 16 + b) * 64 + tid] = s;
        }
    } else {
        const int idx = bid - 640;
        const int b = idx >> 5;
        const int mc = (idx >> 4) & 1;
        const int kc = idx & 15;
        block_softmax(b, mask, attnAll, wred);
        const float* asm_ = attnAll + kc * 128;
        const float4* G4 = reinterpret_cast<const float4*>(graph) +
                           (size_t)b * 2048 * 512 + (size_t)kc * 128 * 512 + mc * 256 + tid;
        float4 acc = make_float4(0.f, 0.f, 0.f, 0.f);
#pragma unroll 8
        for (int k = 0; k < 128; k++) {
            const float a = asm_[k];
            const float4 v = G4[(size_t)k * 512];
            acc.x += a * v.x; acc.y += a * v.y; acc.z += a * v.z; acc.w += a * v.w;
        }
        reinterpret_cast<float4*>(g_onehp)[(kc * 16 + b) * 512 + mc * 256 + tid] = acc;
    }
}

// -------------------- K4: two_hop partials (2048 blocks, 32-k chunks) ---------------
__global__ void __launch_bounds__(256) twohp_kernel(const float* __restrict__ graph) {
    const int idx = 2047 - (int)blockIdx.x;
    const int b = idx >> 7;          // 0..15
    const int mc = (idx >> 6) & 1;
    const int kc = idx & 63;         // 32-k chunk
    const int tid = threadIdx.x;
    __shared__ float osm[32];
    if (tid < 32) {
        float s = 0.f;
#pragma unroll
        for (int p = 0; p < 16; p++)
            s += g_onehp[(p * 16 + b) * 2048 + kc * 32 + tid];
        osm[tid] = s;
    }
    __syncthreads();
    const float4* G4 = reinterpret_cast<const float4*>(graph) +
                       (size_t)b * 2048 * 512 + (size_t)kc * 32 * 512 + mc * 256 + tid;
    float4 acc = make_float4(0.f, 0.f, 0.f, 0.f);
#pragma unroll 8
    for (int k = 31; k >= 0; k--) {
        const float a = osm[k];
        const float4 v = __ldcs(&G4[(size_t)k * 512]);
        acc.x += a * v.x; acc.y += a * v.y; acc.z += a * v.z; acc.w += a * v.w;
    }
    reinterpret_cast<float4*>(g_twohp)[(kc * 16 + b) * 512 + mc * 256 + tid] = acc;
}

// -------------------- K5: finish (tok reduce+norm, c_t, flow_out) -------------------
__global__ void __launch_bounds__(512) finish_kernel(const float* __restrict__ attn,
                                                     float* __restrict__ ct_out,
                                                     float* __restrict__ tok_out,
                                                     float* __restrict__ flow_out) {
    const int b = blockIdx.x, tid = threadIdx.x;
    float4 v0 = make_float4(0.f, 0.f, 0.f, 0.f);
    float4 v1 = make_float4(0.f, 0.f, 0.f, 0.f);
#pragma unroll
    for (int p = 0; p < 8; p++) {
        const float4 a = reinterpret_cast<const float4*>(g_tokp)[(p * 16 + b) * 1024 + tid * 2];
        const float4 c = reinterpret_cast<const float4*>(g_tokp)[(p * 16 + b) * 1024 + tid * 2 + 1];
        v0.x += a.x; v0.y += a.y; v0.z += a.z; v0.w += a.w;
        v1.x += c.x; v1.y += c.y; v1.z += c.z; v1.w += c.w;
    }
    __shared__ float red[512];
    red[tid] = (v0.x + v0.y + v0.z + v0.w) + (v1.x + v1.y + v1.z + v1.w);
    __syncthreads();
    for (int s = 256; s > 0; s >>= 1) {
        if (tid < s) red[tid] += red[tid + s];
        __syncthreads();
    }
    const float inv = 1.0f / red[0];
    float4 o0, o1;
    o0.x = v0.x * inv; o0.y = v0.y * inv; o0.z = v0.z * inv; o0.w = v0.w * inv;
    o1.x = v1.x * inv; o1.y = v1.y * inv; o1.z = v1.z * inv; o1.w = v1.w * inv;
    reinterpret_cast<float4*>(tok_out)[b * 1024 + tid * 2] = o0;
    reinterpret_cast<float4*>(tok_out)[b * 1024 + tid * 2 + 1] = o1;
    if (tid < 256) {
        float s = 0.f;
#pragma unroll
        for (int kc = 0; kc < 8; kc++) s += g_ctp[(kc * 16 + b) * 256 + tid];
        ct_out[b * 256 + tid] = s;
    }
    {
        float4 two = make_float4(0.f, 0.f, 0.f, 0.f);
        float4 one = make_float4(0.f, 0.f, 0.f, 0.f);
#pragma unroll
        for (int p = 0; p < 64; p++) {
            const float4 t = reinterpret_cast<const float4*>(g_twohp)[(p * 16 + b) * 512 + tid];
            two.x += t.x; two.y += t.y; two.z += t.z; two.w += t.w;
        }
#pragma unroll
        for (int p = 0; p < 16; p++) {
            const float4 o = reinterpret_cast<const float4*>(g_onehp)[(p * 16 + b) * 512 + tid];
            one.x += o.x; one.y += o.y; one.z += o.z; one.w += o.w;
        }
        const float4 a = reinterpret_cast<const float4*>(attn)[b * 512 + tid];
        float4 r;
        r.x = 0.33333f * (a.x + one.x + two.x);
        r.y = 0.33333f * (a.y + one.y + two.y);
        r.z = 0.33333f * (a.z + one.z + two.z);
        r.w = 0.33333f * (a.w + one.w + two.w);
        reinterpret_cast<float4*>(flow_out)[b * 512 + tid] = r;
    }
}

// -------------------- launch --------------------------------------------------------
extern "C" void kernel_launch(void* const* d_in, const int* in_sizes, int n_in,
                              void* d_out, int out_size) {
    const float* s_t_hat = (const float*)d_in[0];   // (16, 512)
    const float* enc     = (const float*)d_in[1];   // (16, 2048, 256)
    const float* n2t     = (const float*)d_in[2];   // (16, 2048, 4096)
    const float* mask    = (const float*)d_in[3];   // (16, 2048)
    const float* graph   = (const float*)d_in[4];   // (16, 2048, 2048)
    // d_in[5] = flow, d_in[6] = W_c_w : dead code in reference, never read
    const float* encw    = (const float*)d_in[7];   // (256, 256)
    const float* decw    = (const float*)d_in[8];   // (512, 256)
    const float* decb    = (const float*)d_in[9];   // (256,)
    const float* vw      = (const float*)d_in[10];  // (256, 1)

    float* out      = (float*)d_out;
    float* ct_out   = out;                    // (16, 256)
    float* attn_out = out + 4096;             // (16, 2048)
    float* tok_out  = out + 4096 + 32768;     // (16, 4096)
    float* flow_out = out + 4096 + 32768 + 65536;  // (16, 2048)

    cudaFuncSetAttribute(gemm_scores_kernel, cudaFuncAttributeMaxDynamicSharedMemorySize,
                         GEMM_SMEM);

    prep_kernel<<<80, 256>>>(encw, s_t_hat, decw, decb);
    gemm_scores_kernel<<<148, 256, GEMM_SMEM>>>(enc, vw);
    stream_kernel<<<1152, 256>>>(n2t, enc, graph, mask, attn_out);
    twohp_kernel<<<2048, 256>>>(graph);                // 4th launch -> ncu target
    finish_kernel<<<16, 512>>>(attn_out, ct_out, tok_out, flow_out);
}

// round 12
// speedup vs baseline: 1.0070x; 1.0070x over previous
#include <cuda_runtime.h>
#include <cuda_bf16.h>
#include <cstdint>

// Problem constants
#define Bb 16
#define NK 2048
#define TK 4096
#define Hh 256

// -------------------- scratch (device globals; no allocation) --------------------
__device__ __align__(16) float          g_dec[Bb * Hh];          // dec_fea (16,256)
__device__ __align__(16) __nv_bfloat16  g_wt[Hh * Hh];           // enc_proj^T in bf16, [n][k]
__device__ __align__(16) float          g_scorep[2 * Bb * NK];   // score partials (2 n-halves)
__device__ __align__(16) float          g_ctp[8 * Bb * Hh];      // c_t partials (8 k-chunks)
__device__ __align__(16) float          g_tokp[8 * Bb * TK];     // tok partials (8 k-chunks)
__device__ __align__(16) float          g_onehp[16 * Bb * NK];   // one_hop partials (16 k-chunks)
__device__ __align__(16) float          g_twohp[32 * Bb * NK];   // two_hop partials (32 k-chunks)

// -------------------- K1: W transpose->bf16  +  dec_fea --------------------------
__global__ void __launch_bounds__(256) prep_kernel(const float* __restrict__ encw,
                                                   const float* __restrict__ s_t,
                                                   const float* __restrict__ decw,
                                                   const float* __restrict__ bias) {
    if (blockIdx.x < 64) {
        __shared__ float tile[32][33];
        const int bx = blockIdx.x & 7;        // k tile
        const int by = blockIdx.x >> 3;       // n tile
        const int k0 = bx * 32, n0 = by * 32;
        const int tx = threadIdx.x & 31, ty = threadIdx.x >> 5;
#pragma unroll
        for (int i = 0; i < 32; i += 8)
            tile[ty + i][tx] = encw[(k0 + ty + i) * 256 + n0 + tx];
        __syncthreads();
#pragma unroll
        for (int i = 0; i < 32; i += 8)
            g_wt[(n0 + ty + i) * 256 + k0 + tx] = __float2bfloat16(tile[tx][ty + i]);
    } else {
        const int b = blockIdx.x - 64;
        const int h = threadIdx.x;
        __shared__ float ss[512];
        for (int i = threadIdx.x; i < 512; i += 256) ss[i] = s_t[b * 512 + i];
        __syncthreads();
        float acc = bias[h];
#pragma unroll 8
        for (int j = 0; j < 512; j++) acc += ss[j] * decw[j * 256 + h];
        g_dec[b * 256 + h] = acc;
    }
}

// -------------------- K2: split-N GEMM: 2 blocks/SM, half-W per block --------------
// (R10 configuration — the measured-best full-pipeline GEMM)
#define GEMM_SMEM (128 * 264 * 2 + 64 * 264 * 2 + 64 * 8 * 4 + 128 * 4)

#define LDSM4(r0, r1, r2, r3, addr)                                              \
    asm volatile("ldmatrix.sync.aligned.m8n8.x4.shared.b16 {%0,%1,%2,%3}, [%4];" \
                 : "=r"(r0), "=r"(r1), "=r"(r2), "=r"(r3)                        \
                 : "r"(addr))

#define MMA16816(c, a, b0v, b1v)                                                   \
    asm volatile(                                                                  \
        "mma.sync.aligned.m16n8k16.row.col.f32.bf16.bf16.f32 "                     \
        "{%0,%1,%2,%3},{%4,%5,%6,%7},{%8,%9},{%0,%1,%2,%3};"                       \
        : "+f"(c[0]), "+f"(c[1]), "+f"(c[2]), "+f"(c[3])                           \
        : "r"(a[0]), "r"(a[1]), "r"(a[2]), "r"(a[3]), "r"(b0v), "r"(b1v))

__global__ void __launch_bounds__(256, 2) gemm_scores_kernel(const float* __restrict__ enc,
                                                             const float* __restrict__ vw) {
    extern __shared__ char smraw[];
    __nv_bfloat16* Ws = reinterpret_cast<__nv_bfloat16*>(smraw);   // [128][264]
    __nv_bfloat16* As = Ws + 128 * 264;                            // [64][264]
    float* sred = reinterpret_cast<float*>(As + 64 * 264);         // [64][8]
    float* vs = sred + 64 * 8;                                     // [128]

    const int tid = threadIdx.x;
    const int warp = tid >> 5;      // 0..7
    const int lane = tid & 31;
    const int half = blockIdx.x & 1;

    // Stage this block's W^T half once
    {
        const uint4* src = reinterpret_cast<const uint4*>(g_wt + half * 128 * 256);
        for (int i = tid; i < 4096; i += 256) {
            const int n = i >> 5, c = i & 31;
            *reinterpret_cast<uint4*>(Ws + n * 264 + c * 8) = src[i];
        }
    }
    if (tid < 128) vs[tid] = vw[half * 128 + tid];

    const unsigned AsB = (unsigned)__cvta_generic_to_shared(As);
    const unsigned WsB = (unsigned)__cvta_generic_to_shared(Ws);
    const int n0w = warp * 16;      // 16 N-cols per warp (within half)

    unsigned a_off[4];
#pragma unroll
    for (int mt = 0; mt < 4; mt++)
        a_off[mt] = AsB + 2u * ((unsigned)((mt * 16 + (lane & 15)) * 264 + ((lane >> 4) << 3)));
    const unsigned b_off = WsB + 2u * ((unsigned)((n0w + ((lane >> 4) << 3) + (lane & 7)) * 264 +
                                                  (((lane >> 3) & 1) << 3)));

    const float4* srcBase = reinterpret_cast<const float4*>(enc);

    for (int t = blockIdx.x; t < 1024; t += gridDim.x) {
        const int m0 = (t >> 1) * 64;
        __syncthreads();   // As free, previous sred reads done
        // Stage + convert A tile (64 x 256), fp32 -> bf16 (hidden by co-resident block)
        {
            const float4* s = srcBase + (size_t)(t >> 1) * 4096;
#pragma unroll
            for (int j = 0; j < 16; j++) {
                const int i = tid + j * 256;
                const int r = i >> 6, c = i & 63;
                const float4 f = s[i];
                __nv_bfloat162 p0 = __floats2bfloat162_rn(f.x, f.y);
                __nv_bfloat162 p1 = __floats2bfloat162_rn(f.z, f.w);
                uint2 u;
                u.x = *reinterpret_cast<const unsigned*>(&p0);
                u.y = *reinterpret_cast<const unsigned*>(&p1);
                *reinterpret_cast<uint2*>(As + r * 264 + c * 4) = u;
            }
        }
        __syncthreads();   // As ready

        float acc[4][2][4];
#pragma unroll
        for (int mt = 0; mt < 4; mt++)
#pragma unroll
            for (int nt = 0; nt < 2; nt++)
#pragma unroll
                for (int i = 0; i < 4; i++) acc[mt][nt][i] = 0.0f;

#pragma unroll
        for (int ks = 0; ks < 16; ks++) {
            const unsigned k0b = 2u * (unsigned)(ks * 16);
            unsigned a[4][4];
            unsigned bq[2][2];
#pragma unroll
            for (int mt = 0; mt < 4; mt++)
                LDSM4(a[mt][0], a[mt][1], a[mt][2], a[mt][3], a_off[mt] + k0b);
            {
                unsigned r0, r1, r2, r3;
                LDSM4(r0, r1, r2, r3, b_off + k0b);
                bq[0][0] = r0; bq[0][1] = r1;
                bq[1][0] = r2; bq[1][1] = r3;
            }
#pragma unroll
            for (int mt = 0; mt < 4; mt++)
#pragma unroll
                for (int nt = 0; nt < 2; nt++)
                    MMA16816(acc[mt][nt], a[mt], bq[nt][0], bq[nt][1]);
        }

        // Epilogue: partial score over this half's 128 cols
        const int b = m0 >> 11;
        const float* dec = g_dec + b * 256;
        float decv[4], vv[4];
#pragma unroll
        for (int nt = 0; nt < 2; nt++)
#pragma unroll
            for (int q = 0; q < 2; q++) {
                const int cloc = n0w + nt * 8 + ((lane & 3) << 1) + q;
                decv[nt * 2 + q] = dec[half * 128 + cloc];
                vv[nt * 2 + q] = vs[cloc];
            }
        float rs[4][2] = {{0.f, 0.f}, {0.f, 0.f}, {0.f, 0.f}, {0.f, 0.f}};
#pragma unroll
        for (int mt = 0; mt < 4; mt++)
#pragma unroll
            for (int nt = 0; nt < 2; nt++)
#pragma unroll
                for (int i = 0; i < 4; i++) {
                    const float f = acc[mt][nt][i] + decv[nt * 2 + (i & 1)];
                    rs[mt][i >> 1] += tanhf(f) * vv[nt * 2 + (i & 1)];
                }
#pragma unroll
        for (int mt = 0; mt < 4; mt++)
#pragma unroll
            for (int j = 0; j < 2; j++) {
                float v = rs[mt][j];
                v += __shfl_xor_sync(0xffffffffu, v, 1);
                v += __shfl_xor_sync(0xffffffffu, v, 2);
                if ((lane & 3) == 0)
                    sred[(mt * 16 + (lane >> 2) + j * 8) * 8 + warp] = v;
            }
        __syncthreads();
        if (tid < 64) {
            float s = 0.f;
#pragma unroll
            for (int w = 0; w < 8; w++) s += sred[tid * 8 + w];
            g_scorep[half * 32768 + m0 + tid] = s;
        }
    }
}

// -------------------- block-wide masked softmax into SMEM (deterministic) ----------
__device__ __forceinline__ void block_softmax(int b, const float* __restrict__ mask,
                                              float* attnAll, float* wred) {
    const int tid = threadIdx.x;
    const int lane = tid & 31, wid = tid >> 5;
    const float* sc0 = g_scorep + b * 2048;
    const float* sc1 = g_scorep + 32768 + b * 2048;
    const float* mk = mask + b * 2048;
    float v[8], m[8];
    float lmax = -1e30f;
#pragma unroll
    for (int i = 0; i < 8; i++) {
        v[i] = sc0[tid + i * 256] + sc1[tid + i * 256];
        m[i] = mk[tid + i * 256];
        lmax = fmaxf(lmax, v[i]);
    }
#pragma unroll
    for (int o = 16; o > 0; o >>= 1) lmax = fmaxf(lmax, __shfl_xor_sync(0xffffffffu, lmax, o));
    if (lane == 0) wred[wid] = lmax;
    __syncthreads();
    float gmax = wred[0];
#pragma unroll
    for (int w = 1; w < 8; w++) gmax = fmaxf(gmax, wred[w]);
    __syncthreads();
    float lsum = 0.f;
#pragma unroll
    for (int i = 0; i < 8; i++) {
        v[i] = expf(v[i] - gmax) * m[i];
        lsum += v[i];
    }
#pragma unroll
    for (int o = 16; o > 0; o >>= 1) lsum += __shfl_xor_sync(0xffffffffu, lsum, o);
    if (lane == 0) wred[wid] = lsum;
    __syncthreads();
    float gsum = 0.f;
#pragma unroll
    for (int w = 0; w < 8; w++) gsum += wred[w];
    const float inv = 1.0f / gsum;
#pragma unroll
    for (int i = 0; i < 8; i++) attnAll[tid + i * 256] = v[i] * inv;
    __syncthreads();
}

// -------------------- K3: fused streamer: softmax + tokp + ct + onehp --------------
// blocks [0,512):    tokp   (n2t, __ldcs); tc==0 blocks write attn_out
// blocks [512,640):  ct     (enc, partly L2-hot from gemm)
// blocks [640,1152): onehp  (graph)
__global__ void __launch_bounds__(256) stream_kernel(const float* __restrict__ n2t,
                                                     const float* __restrict__ enc,
                                                     const float* __restrict__ graph,
                                                     const float* __restrict__ mask,
                                                     float* __restrict__ attn_out) {
    const int bid = blockIdx.x;
    const int tid = threadIdx.x;
    __shared__ float attnAll[2048];
    __shared__ float wred[8];
    __shared__ float4 red[256];

    if (bid < 512) {
        const int b = bid >> 5;
        const int tc = (bid >> 3) & 3;
        const int kc = bid & 7;
        block_softmax(b, mask, attnAll, wred);
        if (tc == 0) attn_out[b * 2048 + kc * 256 + tid] = attnAll[kc * 256 + tid];
        const float* asm_ = attnAll + kc * 256;
        const float4* N4 = reinterpret_cast<const float4*>(n2t) +
                           (size_t)b * 2048 * 1024 + (size_t)kc * 256 * 1024 + tc * 256 + tid;
        float4 acc = make_float4(0.f, 0.f, 0.f, 0.f);
#pragma unroll 8
        for (int k = 0; k < 256; k++) {
            const float a = asm_[k];
            const float4 v = __ldcs(&N4[(size_t)k * 1024]);
            acc.x += a * v.x; acc.y += a * v.y; acc.z += a * v.z; acc.w += a * v.w;
        }
        reinterpret_cast<float4*>(g_tokp)[(kc * 16 + b) * 1024 + tc * 256 + tid] = acc;
    } else if (bid < 640) {
        const int idx = bid - 512;
        const int b = idx >> 3, kc = idx & 7;
        const int rg = tid >> 6;
        const int hc = tid & 63;
        block_softmax(b, mask, attnAll, wred);
        const float* asm_ = attnAll + kc * 256;
        const float4* E4 = reinterpret_cast<const float4*>(enc) +
                           (size_t)(b * 2048 + kc * 256) * 64 + hc;
        float4 acc = make_float4(0.f, 0.f, 0.f, 0.f);
#pragma unroll 8
        for (int k = rg; k < 256; k += 4) {
            const float a = asm_[k];
            const float4 e = E4[(size_t)k * 64];
            acc.x += a * e.x; acc.y += a * e.y; acc.z += a * e.z; acc.w += a * e.w;
        }
        red[tid] = acc;
        __syncthreads();
        if (tid < 64) {
            float4 s0 = red[tid], s1 = red[tid + 64], s2 = red[tid + 128], s3 = red[tid + 192];
            float4 s;
            s.x = (s0.x + s1.x) + (s2.x + s3.x);
            s.y = (s0.y + s1.y) + (s2.y + s3.y);
            s.z = (s0.z + s1.z) + (s2.z + s3.z);
            s.w = (s0.w + s1.w) + (s2.w + s3.w);
            reinterpret_cast<float4*>(g_ctp)[(kc * 16 + b) * 64 + tid] = s;
        }
    } else {
        const int idx = bid - 640;
        const int b = idx >> 5;
        const int mc = (idx >> 4) & 1;
        const int kc = idx & 15;
        block_softmax(b, mask, attnAll, wred);
        const float* asm_ = attnAll + kc * 128;
        const float4* G4 = reinterpret_cast<const float4*>(graph) +
                           (size_t)b * 2048 * 512 + (size_t)kc * 128 * 512 + mc * 256 + tid;
        float4 acc = make_float4(0.f, 0.f, 0.f, 0.f);
#pragma unroll 8
        for (int k = 0; k < 128; k++) {
            const float a = asm_[k];
            const float4 v = G4[(size_t)k * 512];
            acc.x += a * v.x; acc.y += a * v.y; acc.z += a * v.z; acc.w += a * v.w;
        }
        reinterpret_cast<float4*>(g_onehp)[(kc * 16 + b) * 512 + mc * 256 + tid] = acc;
    }
}

// -------------------- K4: two_hop partials (1024 blocks, 64-k chunks) ---------------
__global__ void __launch_bounds__(256) twohp_kernel(const float* __restrict__ graph) {
    const int idx = 1023 - (int)blockIdx.x;
    const int b = idx >> 6;
    const int mc = (idx >> 5) & 1;
    const int kc2 = idx & 31;
    const int tid = threadIdx.x;
    __shared__ float osm[64];
    if (tid < 64) {
        float s = 0.f;
#pragma unroll
        for (int p = 0; p < 16; p++)
            s += g_onehp[(p * 16 + b) * 2048 + kc2 * 64 + tid];
        osm[tid] = s;
    }
    __syncthreads();
    const float4* G4 = reinterpret_cast<const float4*>(graph) +
                       (size_t)b * 2048 * 512 + (size_t)kc2 * 64 * 512 + mc * 256 + tid;
    float4 acc = make_float4(0.f, 0.f, 0.f, 0.f);
#pragma unroll 8
    for (int k = 63; k >= 0; k--) {
        const float a = osm[k];
        const float4 v = __ldcs(&G4[(size_t)k * 512]);
        acc.x += a * v.x; acc.y += a * v.y; acc.z += a * v.z; acc.w += a * v.w;
    }
    reinterpret_cast<float4*>(g_twohp)[(kc2 * 16 + b) * 512 + mc * 256 + tid] = acc;
}

// -------------------- K5: finish (tok reduce+norm, c_t, flow_out) -------------------
__global__ void __launch_bounds__(512) finish_kernel(const float* __restrict__ attn,
                                                     float* __restrict__ ct_out,
                                                     float* __restrict__ tok_out,
                                                     float* __restrict__ flow_out) {
    const int b = blockIdx.x, tid = threadIdx.x;
    float4 v0 = make_float4(0.f, 0.f, 0.f, 0.f);
    float4 v1 = make_float4(0.f, 0.f, 0.f, 0.f);
#pragma unroll
    for (int p = 0; p < 8; p++) {
        const float4 a = reinterpret_cast<const float4*>(g_tokp)[(p * 16 + b) * 1024 + tid * 2];
        const float4 c = reinterpret_cast<const float4*>(g_tokp)[(p * 16 + b) * 1024 + tid * 2 + 1];
        v0.x += a.x; v0.y += a.y; v0.z += a.z; v0.w += a.w;
        v1.x += c.x; v1.y += c.y; v1.z += c.z; v1.w += c.w;
    }
    __shared__ float red[512];
    red[tid] = (v0.x + v0.y + v0.z + v0.w) + (v1.x + v1.y + v1.z + v1.w);
    __syncthreads();
    for (int s = 256; s > 0; s >>= 1) {
        if (tid < s) red[tid] += red[tid + s];
        __syncthreads();
    }
    const float inv = 1.0f / red[0];
    float4 o0, o1;
    o0.x = v0.x * inv; o0.y = v0.y * inv; o0.z = v0.z * inv; o0.w = v0.w * inv;
    o1.x = v1.x * inv; o1.y = v1.y * inv; o1.z = v1.z * inv; o1.w = v1.w * inv;
    reinterpret_cast<float4*>(tok_out)[b * 1024 + tid * 2] = o0;
    reinterpret_cast<float4*>(tok_out)[b * 1024 + tid * 2 + 1] = o1;
    if (tid < 256) {
        float s = 0.f;
#pragma unroll
        for (int kc = 0; kc < 8; kc++) s += g_ctp[(kc * 16 + b) * 256 + tid];
        ct_out[b * 256 + tid] = s;
    }
    {
        float4 two = make_float4(0.f, 0.f, 0.f, 0.f);
        float4 one = make_float4(0.f, 0.f, 0.f, 0.f);
#pragma unroll
        for (int p = 0; p < 32; p++) {
            const float4 t = reinterpret_cast<const float4*>(g_twohp)[(p * 16 + b) * 512 + tid];
            two.x += t.x; two.y += t.y; two.z += t.z; two.w += t.w;
        }
#pragma unroll
        for (int p = 0; p < 16; p++) {
            const float4 o = reinterpret_cast<const float4*>(g_onehp)[(p * 16 + b) * 512 + tid];
            one.x += o.x; one.y += o.y; one.z += o.z; one.w += o.w;
        }
        const float4 a = reinterpret_cast<const float4*>(attn)[b * 512 + tid];
        float4 r;
        r.x = 0.33333f * (a.x + one.x + two.x);
        r.y = 0.33333f * (a.y + one.y + two.y);
        r.z = 0.33333f * (a.z + one.z + two.z);
        r.w = 0.33333f * (a.w + one.w + two.w);
        reinterpret_cast<float4*>(flow_out)[b * 512 + tid] = r;
    }
}

// -------------------- launch --------------------------------------------------------
extern "C" void kernel_launch(void* const* d_in, const int* in_sizes, int n_in,
                              void* d_out, int out_size) {
    const float* s_t_hat = (const float*)d_in[0];   // (16, 512)
    const float* enc     = (const float*)d_in[1];   // (16, 2048, 256)
    const float* n2t     = (const float*)d_in[2];   // (16, 2048, 4096)
    const float* mask    = (const float*)d_in[3];   // (16, 2048)
    const float* graph   = (const float*)d_in[4];   // (16, 2048, 2048)
    // d_in[5] = flow, d_in[6] = W_c_w : dead code in reference, never read
    const float* encw    = (const float*)d_in[7];   // (256, 256)
    const float* decw    = (const float*)d_in[8];   // (512, 256)
    const float* decb    = (const float*)d_in[9];   // (256,)
    const float* vw      = (const float*)d_in[10];  // (256, 1)

    float* out      = (float*)d_out;
    float* ct_out   = out;                    // (16, 256)
    float* attn_out = out + 4096;             // (16, 2048)
    float* tok_out  = out + 4096 + 32768;     // (16, 4096)
    float* flow_out = out + 4096 + 32768 + 65536;  // (16, 2048)

    cudaFuncSetAttribute(gemm_scores_kernel, cudaFuncAttributeMaxDynamicSharedMemorySize,
                         GEMM_SMEM);

    prep_kernel<<<80, 256>>>(encw, s_t_hat, decw, decb);
    gemm_scores_kernel<<<296, 256, GEMM_SMEM>>>(enc, vw);
    stream_kernel<<<1152, 256>>>(n2t, enc, graph, mask, attn_out);
    twohp_kernel<<<1024, 256>>>(graph);                // 4th launch -> ncu target
    finish_kernel<<<16, 512>>>(attn_out, ct_out, tok_out, flow_out);
}

// round 13
// speedup vs baseline: 1.0081x; 1.0011x over previous
#include <cuda_runtime.h>
#include <cuda_bf16.h>
#include <cstdint>

// Problem constants
#define Bb 16
#define NK 2048
#define TK 4096
#define Hh 256

// -------------------- scratch (device globals; no allocation) --------------------
__device__ __align__(16) float          g_dec[Bb * Hh];          // dec_fea (16,256)
__device__ __align__(16) __nv_bfloat16  g_wt[Hh * Hh];           // enc_proj^T in bf16, [n][k]
__device__ __align__(16) float          g_scorep[2 * Bb * NK];   // score partials (2 n-halves)
__device__ __align__(16) float          g_ctp[8 * Bb * Hh];      // c_t partials (8 k-chunks)
__device__ __align__(16) float          g_tokp[8 * Bb * TK];     // tok partials (8 k-chunks)
__device__ __align__(16) float          g_onehp[16 * Bb * NK];   // one_hop partials (16 k-chunks)
__device__ __align__(16) float          g_twohp[32 * Bb * NK];   // two_hop partials (32 k-chunks)

// -------------------- K1: W transpose -> bf16 [n][k] ------------------------------
__global__ void __launch_bounds__(256) prep_wt_kernel(const float* __restrict__ encw) {
    __shared__ float tile[32][33];
    const int bx = blockIdx.x & 7;        // k tile
    const int by = blockIdx.x >> 3;       // n tile
    const int k0 = bx * 32, n0 = by * 32;
    const int tx = threadIdx.x & 31, ty = threadIdx.x >> 5;
#pragma unroll
    for (int i = 0; i < 32; i += 8)
        tile[ty + i][tx] = encw[(k0 + ty + i) * 256 + n0 + tx];
    __syncthreads();
#pragma unroll
    for (int i = 0; i < 32; i += 8)
        g_wt[(n0 + ty + i) * 256 + k0 + tx] = __float2bfloat16(tile[tx][ty + i]);
}

// -------------------- K2: dec_fea -------------------------------------------------
__global__ void __launch_bounds__(256) dec_fea_kernel(const float* __restrict__ s_t,
                                                      const float* __restrict__ decw,
                                                      const float* __restrict__ bias) {
    const int b = blockIdx.x;
    const int h = threadIdx.x;
    __shared__ float ss[512];
    for (int i = threadIdx.x; i < 512; i += 256) ss[i] = s_t[b * 512 + i];
    __syncthreads();
    float acc = bias[h];
#pragma unroll 8
    for (int j = 0; j < 512; j++) acc += ss[j] * decw[j * 256 + h];
    g_dec[b * 256 + h] = acc;
}

// -------------------- K3: split-N GEMM: 2 blocks/SM, half-W per block --------------
// (R10 configuration — the measured-best full-pipeline GEMM)
#define GEMM_SMEM (128 * 264 * 2 + 64 * 264 * 2 + 64 * 8 * 4 + 128 * 4)

#define LDSM4(r0, r1, r2, r3, addr)                                              \
    asm volatile("ldmatrix.sync.aligned.m8n8.x4.shared.b16 {%0,%1,%2,%3}, [%4];" \
                 : "=r"(r0), "=r"(r1), "=r"(r2), "=r"(r3)                        \
                 : "r"(addr))

#define MMA16816(c, a, b0v, b1v)                                                   \
    asm volatile(                                                                  \
        "mma.sync.aligned.m16n8k16.row.col.f32.bf16.bf16.f32 "                     \
        "{%0,%1,%2,%3},{%4,%5,%6,%7},{%8,%9},{%0,%1,%2,%3};"                       \
        : "+f"(c[0]), "+f"(c[1]), "+f"(c[2]), "+f"(c[3])                           \
        : "r"(a[0]), "r"(a[1]), "r"(a[2]), "r"(a[3]), "r"(b0v), "r"(b1v))

__global__ void __launch_bounds__(256, 2) gemm_scores_kernel(const float* __restrict__ enc,
                                                             const float* __restrict__ vw) {
    extern __shared__ char smraw[];
    __nv_bfloat16* Ws = reinterpret_cast<__nv_bfloat16*>(smraw);   // [128][264]
    __nv_bfloat16* As = Ws + 128 * 264;                            // [64][264]
    float* sred = reinterpret_cast<float*>(As + 64 * 264);         // [64][8]
    float* vs = sred + 64 * 8;                                     // [128]

    const int tid = threadIdx.x;
    const int warp = tid >> 5;      // 0..7
    const int lane = tid & 31;
    const int half = blockIdx.x & 1;

    // Stage this block's W^T half once
    {
        const uint4* src = reinterpret_cast<const uint4*>(g_wt + half * 128 * 256);
        for (int i = tid; i < 4096; i += 256) {
            const int n = i >> 5, c = i & 31;
            *reinterpret_cast<uint4*>(Ws + n * 264 + c * 8) = src[i];
        }
    }
    if (tid < 128) vs[tid] = vw[half * 128 + tid];

    const unsigned AsB = (unsigned)__cvta_generic_to_shared(As);
    const unsigned WsB = (unsigned)__cvta_generic_to_shared(Ws);
    const int n0w = warp * 16;      // 16 N-cols per warp (within half)

    unsigned a_off[4];
#pragma unroll
    for (int mt = 0; mt < 4; mt++)
        a_off[mt] = AsB + 2u * ((unsigned)((mt * 16 + (lane & 15)) * 264 + ((lane >> 4) << 3)));
    const unsigned b_off = WsB + 2u * ((unsigned)((n0w + ((lane >> 4) << 3) + (lane & 7)) * 264 +
                                                  (((lane >> 3) & 1) << 3)));

    const float4* srcBase = reinterpret_cast<const float4*>(enc);

    for (int t = blockIdx.x; t < 1024; t += gridDim.x) {
        const int m0 = (t >> 1) * 64;
        __syncthreads();   // As free, previous sred reads done
        // Stage + convert A tile (64 x 256), fp32 -> bf16 (hidden by co-resident block)
        {
            const float4* s = srcBase + (size_t)(t >> 1) * 4096;
#pragma unroll
            for (int j = 0; j < 16; j++) {
                const int i = tid + j * 256;
                const int r = i >> 6, c = i & 63;
                const float4 f = s[i];
                __nv_bfloat162 p0 = __floats2bfloat162_rn(f.x, f.y);
                __nv_bfloat162 p1 = __floats2bfloat162_rn(f.z, f.w);
                uint2 u;
                u.x = *reinterpret_cast<const unsigned*>(&p0);
                u.y = *reinterpret_cast<const unsigned*>(&p1);
                *reinterpret_cast<uint2*>(As + r * 264 + c * 4) = u;
            }
        }
        __syncthreads();   // As ready

        float acc[4][2][4];
#pragma unroll
        for (int mt = 0; mt < 4; mt++)
#pragma unroll
            for (int nt = 0; nt < 2; nt++)
#pragma unroll
                for (int i = 0; i < 4; i++) acc[mt][nt][i] = 0.0f;

#pragma unroll
        for (int ks = 0; ks < 16; ks++) {
            const unsigned k0b = 2u * (unsigned)(ks * 16);
            unsigned a[4][4];
            unsigned bq[2][2];
#pragma unroll
            for (int mt = 0; mt < 4; mt++)
                LDSM4(a[mt][0], a[mt][1], a[mt][2], a[mt][3], a_off[mt] + k0b);
            {
                unsigned r0, r1, r2, r3;
                LDSM4(r0, r1, r2, r3, b_off + k0b);
                bq[0][0] = r0; bq[0][1] = r1;
                bq[1][0] = r2; bq[1][1] = r3;
            }
#pragma unroll
            for (int mt = 0; mt < 4; mt++)
#pragma unroll
                for (int nt = 0; nt < 2; nt++)
                    MMA16816(acc[mt][nt], a[mt], bq[nt][0], bq[nt][1]);
        }

        // Epilogue: partial score over this half's 128 cols
        const int b = m0 >> 11;
        const float* dec = g_dec + b * 256;
        float decv[4], vv[4];
#pragma unroll
        for (int nt = 0; nt < 2; nt++)
#pragma unroll
            for (int q = 0; q < 2; q++) {
                const int cloc = n0w + nt * 8 + ((lane & 3) << 1) + q;
                decv[nt * 2 + q] = dec[half * 128 + cloc];
                vv[nt * 2 + q] = vs[cloc];
            }
        float rs[4][2] = {{0.f, 0.f}, {0.f, 0.f}, {0.f, 0.f}, {0.f, 0.f}};
#pragma unroll
        for (int mt = 0; mt < 4; mt++)
#pragma unroll
            for (int nt = 0; nt < 2; nt++)
#pragma unroll
                for (int i = 0; i < 4; i++) {
                    const float f = acc[mt][nt][i] + decv[nt * 2 + (i & 1)];
                    rs[mt][i >> 1] += tanhf(f) * vv[nt * 2 + (i & 1)];
                }
#pragma unroll
        for (int mt = 0; mt < 4; mt++)
#pragma unroll
            for (int j = 0; j < 2; j++) {
                float v = rs[mt][j];
                v += __shfl_xor_sync(0xffffffffu, v, 1);
                v += __shfl_xor_sync(0xffffffffu, v, 2);
                if ((lane & 3) == 0)
                    sred[(mt * 16 + (lane >> 2) + j * 8) * 8 + warp] = v;
            }
        __syncthreads();
        if (tid < 64) {
            float s = 0.f;
#pragma unroll
            for (int w = 0; w < 8; w++) s += sred[tid * 8 + w];
            g_scorep[half * 32768 + m0 + tid] = s;
        }
    }
}

// -------------------- block-wide masked softmax into SMEM (deterministic) ----------
__device__ __forceinline__ void block_softmax(int b, const float* __restrict__ mask,
                                              float* attnAll, float* wred) {
    const int tid = threadIdx.x;
    const int lane = tid & 31, wid = tid >> 5;
    const float* sc0 = g_scorep + b * 2048;
    const float* sc1 = g_scorep + 32768 + b * 2048;
    const float* mk = mask + b * 2048;
    float v[8], m[8];
    float lmax = -1e30f;
#pragma unroll
    for (int i = 0; i < 8; i++) {
        v[i] = sc0[tid + i * 256] + sc1[tid + i * 256];
        m[i] = mk[tid + i * 256];
        lmax = fmaxf(lmax, v[i]);
    }
#pragma unroll
    for (int o = 16; o > 0; o >>= 1) lmax = fmaxf(lmax, __shfl_xor_sync(0xffffffffu, lmax, o));
    if (lane == 0) wred[wid] = lmax;
    __syncthreads();
    float gmax = wred[0];
#pragma unroll
    for (int w = 1; w < 8; w++) gmax = fmaxf(gmax, wred[w]);
    __syncthreads();
    float lsum = 0.f;
#pragma unroll
    for (int i = 0; i < 8; i++) {
        v[i] = expf(v[i] - gmax) * m[i];
        lsum += v[i];
    }
#pragma unroll
    for (int o = 16; o > 0; o >>= 1) lsum += __shfl_xor_sync(0xffffffffu, lsum, o);
    if (lane == 0) wred[wid] = lsum;
    __syncthreads();
    float gsum = 0.f;
#pragma unroll
    for (int w = 0; w < 8; w++) gsum += wred[w];
    const float inv = 1.0f / gsum;
#pragma unroll
    for (int i = 0; i < 8; i++) attnAll[tid + i * 256] = v[i] * inv;
    __syncthreads();
}

// -------------------- K4: fused streamer: softmax + tokp + ct + onehp --------------
// blocks [0,512):    tokp   (n2t, __ldcs); tc==0 blocks write attn_out
// blocks [512,640):  ct     (enc, partly L2-hot from gemm)
// blocks [640,1152): onehp  (graph)
__global__ void __launch_bounds__(256) stream_kernel(const float* __restrict__ n2t,
                                                     const float* __restrict__ enc,
                                                     const float* __restrict__ graph,
                                                     const float* __restrict__ mask,
                                                     float* __restrict__ attn_out) {
    const int bid = blockIdx.x;
    const int tid = threadIdx.x;
    __shared__ float attnAll[2048];
    __shared__ float wred[8];
    __shared__ float4 red[256];

    if (bid < 512) {
        const int b = bid >> 5;
        const int tc = (bid >> 3) & 3;
        const int kc = bid & 7;
        block_softmax(b, mask, attnAll, wred);
        if (tc == 0) attn_out[b * 2048 + kc * 256 + tid] = attnAll[kc * 256 + tid];
        const float* asm_ = attnAll + kc * 256;
        const float4* N4 = reinterpret_cast<const float4*>(n2t) +
                           (size_t)b * 2048 * 1024 + (size_t)kc * 256 * 1024 + tc * 256 + tid;
        float4 acc = make_float4(0.f, 0.f, 0.f, 0.f);
#pragma unroll 8
        for (int k = 0; k < 256; k++) {
            const float a = asm_[k];
            const float4 v = __ldcs(&N4[(size_t)k * 1024]);
            acc.x += a * v.x; acc.y += a * v.y; acc.z += a * v.z; acc.w += a * v.w;
        }
        reinterpret_cast<float4*>(g_tokp)[(kc * 16 + b) * 1024 + tc * 256 + tid] = acc;
    } else if (bid < 640) {
        const int idx = bid - 512;
        const int b = idx >> 3, kc = idx & 7;
        const int rg = tid >> 6;
        const int hc = tid & 63;
        block_softmax(b, mask, attnAll, wred);
        const float* asm_ = attnAll + kc * 256;
        const float4* E4 = reinterpret_cast<const float4*>(enc) +
                           (size_t)(b * 2048 + kc * 256) * 64 + hc;
        float4 acc = make_float4(0.f, 0.f, 0.f, 0.f);
#pragma unroll 8
        for (int k = rg; k < 256; k += 4) {
            const float a = asm_[k];
            const float4 e = E4[(size_t)k * 64];
            acc.x += a * e.x; acc.y += a * e.y; acc.z += a * e.z; acc.w += a * e.w;
        }
        red[tid] = acc;
        __syncthreads();
        if (tid < 64) {
            float4 s0 = red[tid], s1 = red[tid + 64], s2 = red[tid + 128], s3 = red[tid + 192];
            float4 s;
            s.x = (s0.x + s1.x) + (s2.x + s3.x);
            s.y = (s0.y + s1.y) + (s2.y + s3.y);
            s.z = (s0.z + s1.z) + (s2.z + s3.z);
            s.w = (s0.w + s1.w) + (s2.w + s3.w);
            reinterpret_cast<float4*>(g_ctp)[(kc * 16 + b) * 64 + tid] = s;
        }
    } else {
        const int idx = bid - 640;
        const int b = idx >> 5;
        const int mc = (idx >> 4) & 1;
        const int kc = idx & 15;
        block_softmax(b, mask, attnAll, wred);
        const float* asm_ = attnAll + kc * 128;
        const float4* G4 = reinterpret_cast<const float4*>(graph) +
                           (size_t)b * 2048 * 512 + (size_t)kc * 128 * 512 + mc * 256 + tid;
        float4 acc = make_float4(0.f, 0.f, 0.f, 0.f);
#pragma unroll 8
        for (int k = 0; k < 128; k++) {
            const float a = asm_[k];
            const float4 v = G4[(size_t)k * 512];
            acc.x += a * v.x; acc.y += a * v.y; acc.z += a * v.z; acc.w += a * v.w;
        }
        reinterpret_cast<float4*>(g_onehp)[(kc * 16 + b) * 512 + mc * 256 + tid] = acc;
    }
}

// -------------------- K5: two_hop partials (1024 blocks, forward streaming) ---------
__global__ void __launch_bounds__(256) twohp_kernel(const float* __restrict__ graph) {
    const int idx = (int)blockIdx.x;
    const int b = idx >> 6;
    const int mc = (idx >> 5) & 1;
    const int kc2 = idx & 31;
    const int tid = threadIdx.x;
    __shared__ float osm[64];
    if (tid < 64) {
        float s = 0.f;
#pragma unroll
        for (int p = 0; p < 16; p++)
            s += g_onehp[(p * 16 + b) * 2048 + kc2 * 64 + tid];
        osm[tid] = s;
    }
    __syncthreads();
    const float4* G4 = reinterpret_cast<const float4*>(graph) +
                       (size_t)b * 2048 * 512 + (size_t)kc2 * 64 * 512 + mc * 256 + tid;
    float4 acc = make_float4(0.f, 0.f, 0.f, 0.f);
#pragma unroll 8
    for (int k = 0; k < 64; k++) {
        const float a = osm[k];
        const float4 v = __ldcs(&G4[(size_t)k * 512]);
        acc.x += a * v.x; acc.y += a * v.y; acc.z += a * v.z; acc.w += a * v.w;
    }
    reinterpret_cast<float4*>(g_twohp)[(kc2 * 16 + b) * 512 + mc * 256 + tid] = acc;
}

// -------------------- K6: finish (tok reduce+norm, c_t, flow_out) -------------------
__global__ void __launch_bounds__(512) finish_kernel(const float* __restrict__ attn,
                                                     float* __restrict__ ct_out,
                                                     float* __restrict__ tok_out,
                                                     float* __restrict__ flow_out) {
    const int b = blockIdx.x, tid = threadIdx.x;
    float4 v0 = make_float4(0.f, 0.f, 0.f, 0.f);
    float4 v1 = make_float4(0.f, 0.f, 0.f, 0.f);
#pragma unroll
    for (int p = 0; p < 8; p++) {
        const float4 a = reinterpret_cast<const float4*>(g_tokp)[(p * 16 + b) * 1024 + tid * 2];
        const float4 c = reinterpret_cast<const float4*>(g_tokp)[(p * 16 + b) * 1024 + tid * 2 + 1];
        v0.x += a.x; v0.y += a.y; v0.z += a.z; v0.w += a.w;
        v1.x += c.x; v1.y += c.y; v1.z += c.z; v1.w += c.w;
    }
    __shared__ float red[512];
    red[tid] = (v0.x + v0.y + v0.z + v0.w) + (v1.x + v1.y + v1.z + v1.w);
    __syncthreads();
    for (int s = 256; s > 0; s >>= 1) {
        if (tid < s) red[tid] += red[tid + s];
        __syncthreads();
    }
    const float inv = 1.0f / red[0];
    float4 o0, o1;
    o0.x = v0.x * inv; o0.y = v0.y * inv; o0.z = v0.z * inv; o0.w = v0.w * inv;
    o1.x = v1.x * inv; o1.y = v1.y * inv; o1.z = v1.z * inv; o1.w = v1.w * inv;
    reinterpret_cast<float4*>(tok_out)[b * 1024 + tid * 2] = o0;
    reinterpret_cast<float4*>(tok_out)[b * 1024 + tid * 2 + 1] = o1;
    if (tid < 256) {
        float s = 0.f;
#pragma unroll
        for (int kc = 0; kc < 8; kc++) s += g_ctp[(kc * 16 + b) * 256 + tid];
        ct_out[b * 256 + tid] = s;
    }
    {
        float4 two = make_float4(0.f, 0.f, 0.f, 0.f);
        float4 one = make_float4(0.f, 0.f, 0.f, 0.f);
#pragma unroll
        for (int p = 0; p < 32; p++) {
            const float4 t = reinterpret_cast<const float4*>(g_twohp)[(p * 16 + b) * 512 + tid];
            two.x += t.x; two.y += t.y; two.z += t.z; two.w += t.w;
        }
#pragma unroll
        for (int p = 0; p < 16; p++) {
            const float4 o = reinterpret_cast<const float4*>(g_onehp)[(p * 16 + b) * 512 + tid];
            one.x += o.x; one.y += o.y; one.z += o.z; one.w += o.w;
        }
        const float4 a = reinterpret_cast<const float4*>(attn)[b * 512 + tid];
        float4 r;
        r.x = 0.33333f * (a.x + one.x + two.x);
        r.y = 0.33333f * (a.y + one.y + two.y);
        r.z = 0.33333f * (a.z + one.z + two.z);
        r.w = 0.33333f * (a.w + one.w + two.w);
        reinterpret_cast<float4*>(flow_out)[b * 512 + tid] = r;
    }
}

// -------------------- launch --------------------------------------------------------
extern "C" void kernel_launch(void* const* d_in, const int* in_sizes, int n_in,
                              void* d_out, int out_size) {
    const float* s_t_hat = (const float*)d_in[0];   // (16, 512)
    const float* enc     = (const float*)d_in[1];   // (16, 2048, 256)
    const float* n2t     = (const float*)d_in[2];   // (16, 2048, 4096)
    const float* mask    = (const float*)d_in[3];   // (16, 2048)
    const float* graph   = (const float*)d_in[4];   // (16, 2048, 2048)
    // d_in[5] = flow, d_in[6] = W_c_w : dead code in reference, never read
    const float* encw    = (const float*)d_in[7];   // (256, 256)
    const float* decw    = (const float*)d_in[8];   // (512, 256)
    const float* decb    = (const float*)d_in[9];   // (256,)
    const float* vw      = (const float*)d_in[10];  // (256, 1)

    float* out      = (float*)d_out;
    float* ct_out   = out;                    // (16, 256)
    float* attn_out = out + 4096;             // (16, 2048)
    float* tok_out  = out + 4096 + 32768;     // (16, 4096)
    float* flow_out = out + 4096 + 32768 + 65536;  // (16, 2048)

    cudaFuncSetAttribute(gemm_scores_kernel, cudaFuncAttributeMaxDynamicSharedMemorySize,
                         GEMM_SMEM);

    prep_wt_kernel<<<64, 256>>>(encw);
    dec_fea_kernel<<<16, 256>>>(s_t_hat, decw, decb);
    gemm_scores_kernel<<<296, 256, GEMM_SMEM>>>(enc, vw);
    stream_kernel<<<1152, 256>>>(n2t, enc, graph, mask, attn_out);
    twohp_kernel<<<1024, 256>>>(graph);                // 4th launch -> ncu target... (5th here)
    finish_kernel<<<16, 512>>>(attn_out, ct_out, tok_out, flow_out);
}

// round 14
// speedup vs baseline: 1.0177x; 1.0095x over previous
#include <cuda_runtime.h>
#include <cuda_bf16.h>
#include <cstdint>

// Problem constants
#define Bb 16
#define NK 2048
#define TK 4096
#define Hh 256

// -------------------- scratch (device globals; no allocation) --------------------
__device__ __align__(16) float          g_dec[Bb * Hh];          // dec_fea (16,256)
__device__ __align__(16) __nv_bfloat16  g_wt[Hh * Hh];           // enc_proj^T in bf16, [n][k]
__device__ __align__(16) float          g_scorep[2 * Bb * NK];   // score partials (2 n-halves)
__device__ __align__(16) float          g_ctp[8 * Bb * Hh];      // c_t partials (8 k-chunks)
__device__ __align__(16) float          g_tokp[8 * Bb * TK];     // tok partials (8 k-chunks)
__device__ __align__(16) float          g_onehp[16 * Bb * NK];   // one_hop partials (16 k-chunks)
__device__ __align__(16) float          g_twohp[32 * Bb * NK];   // two_hop partials (32 k-chunks)

// -------------------- K1: W transpose -> bf16 [n][k] ------------------------------
__global__ void __launch_bounds__(256) prep_wt_kernel(const float* __restrict__ encw) {
    __shared__ float tile[32][33];
    const int bx = blockIdx.x & 7;        // k tile
    const int by = blockIdx.x >> 3;       // n tile
    const int k0 = bx * 32, n0 = by * 32;
    const int tx = threadIdx.x & 31, ty = threadIdx.x >> 5;
#pragma unroll
    for (int i = 0; i < 32; i += 8)
        tile[ty + i][tx] = encw[(k0 + ty + i) * 256 + n0 + tx];
    __syncthreads();
#pragma unroll
    for (int i = 0; i < 32; i += 8)
        g_wt[(n0 + ty + i) * 256 + k0 + tx] = __float2bfloat16(tile[tx][ty + i]);
}

// -------------------- K2: dec_fea -------------------------------------------------
__global__ void __launch_bounds__(256) dec_fea_kernel(const float* __restrict__ s_t,
                                                      const float* __restrict__ decw,
                                                      const float* __restrict__ bias) {
    const int b = blockIdx.x;
    const int h = threadIdx.x;
    __shared__ float ss[512];
    for (int i = threadIdx.x; i < 512; i += 256) ss[i] = s_t[b * 512 + i];
    __syncthreads();
    float acc = bias[h];
#pragma unroll 8
    for (int j = 0; j < 512; j++) acc += ss[j] * decw[j * 256 + h];
    g_dec[b * 256 + h] = acc;
}

// -------------------- K3: tiny filler (launch spacing, matches champion config) ----
__global__ void zero_kernel() { g_tokp[threadIdx.x] = 0.0f; }   // fully overwritten later

// -------------------- K4: split-N GEMM: 2 blocks/SM, half-W per block --------------
#define GEMM_SMEM (128 * 264 * 2 + 64 * 264 * 2 + 64 * 8 * 4 + 128 * 4)

#define LDSM4(r0, r1, r2, r3, addr)                                              \
    asm volatile("ldmatrix.sync.aligned.m8n8.x4.shared.b16 {%0,%1,%2,%3}, [%4];" \
                 : "=r"(r0), "=r"(r1), "=r"(r2), "=r"(r3)                        \
                 : "r"(addr))

#define MMA16816(c, a, b0v, b1v)                                                   \
    asm volatile(                                                                  \
        "mma.sync.aligned.m16n8k16.row.col.f32.bf16.bf16.f32 "                     \
        "{%0,%1,%2,%3},{%4,%5,%6,%7},{%8,%9},{%0,%1,%2,%3};"                       \
        : "+f"(c[0]), "+f"(c[1]), "+f"(c[2]), "+f"(c[3])                           \
        : "r"(a[0]), "r"(a[1]), "r"(a[2]), "r"(a[3]), "r"(b0v), "r"(b1v))

__global__ void __launch_bounds__(256, 2) gemm_scores_kernel(const float* __restrict__ enc,
                                                             const float* __restrict__ vw) {
    extern __shared__ char smraw[];
    __nv_bfloat16* Ws = reinterpret_cast<__nv_bfloat16*>(smraw);   // [128][264]
    __nv_bfloat16* As = Ws + 128 * 264;                            // [64][264]
    float* sred = reinterpret_cast<float*>(As + 64 * 264);         // [64][8]
    float* vs = sred + 64 * 8;                                     // [128]

    const int tid = threadIdx.x;
    const int warp = tid >> 5;      // 0..7
    const int lane = tid & 31;
    const int half = blockIdx.x & 1;

    // Stage this block's W^T half once
    {
        const uint4* src = reinterpret_cast<const uint4*>(g_wt + half * 128 * 256);
        for (int i = tid; i < 4096; i += 256) {
            const int n = i >> 5, c = i & 31;
            *reinterpret_cast<uint4*>(Ws + n * 264 + c * 8) = src[i];
        }
    }
    if (tid < 128) vs[tid] = vw[half * 128 + tid];

    const unsigned AsB = (unsigned)__cvta_generic_to_shared(As);
    const unsigned WsB = (unsigned)__cvta_generic_to_shared(Ws);
    const int n0w = warp * 16;      // 16 N-cols per warp (within half)

    unsigned a_off[4];
#pragma unroll
    for (int mt = 0; mt < 4; mt++)
        a_off[mt] = AsB + 2u * ((unsigned)((mt * 16 + (lane & 15)) * 264 + ((lane >> 4) << 3)));
    const unsigned b_off = WsB + 2u * ((unsigned)((n0w + ((lane >> 4) << 3) + (lane & 7)) * 264 +
                                                  (((lane >> 3) & 1) << 3)));

    const float4* srcBase = reinterpret_cast<const float4*>(enc);

    for (int t = blockIdx.x; t < 1024; t += gridDim.x) {
        const int m0 = (t >> 1) * 64;
        __syncthreads();   // As free, previous sred reads done
        // Stage + convert A tile (64 x 256), fp32 -> bf16 (hidden by co-resident block)
        {
            const float4* s = srcBase + (size_t)(t >> 1) * 4096;
#pragma unroll
            for (int j = 0; j < 16; j++) {
                const int i = tid + j * 256;
                const int r = i >> 6, c = i & 63;
                const float4 f = s[i];
                __nv_bfloat162 p0 = __floats2bfloat162_rn(f.x, f.y);
                __nv_bfloat162 p1 = __floats2bfloat162_rn(f.z, f.w);
                uint2 u;
                u.x = *reinterpret_cast<const unsigned*>(&p0);
                u.y = *reinterpret_cast<const unsigned*>(&p1);
                *reinterpret_cast<uint2*>(As + r * 264 + c * 4) = u;
            }
        }
        __syncthreads();   // As ready

        float acc[4][2][4];
#pragma unroll
        for (int mt = 0; mt < 4; mt++)
#pragma unroll
            for (int nt = 0; nt < 2; nt++)
#pragma unroll
                for (int i = 0; i < 4; i++) acc[mt][nt][i] = 0.0f;

#pragma unroll
        for (int ks = 0; ks < 16; ks++) {
            const unsigned k0b = 2u * (unsigned)(ks * 16);
            unsigned a[4][4];
            unsigned bq[2][2];
#pragma unroll
            for (int mt = 0; mt < 4; mt++)
                LDSM4(a[mt][0], a[mt][1], a[mt][2], a[mt][3], a_off[mt] + k0b);
            {
                unsigned r0, r1, r2, r3;
                LDSM4(r0, r1, r2, r3, b_off + k0b);
                bq[0][0] = r0; bq[0][1] = r1;
                bq[1][0] = r2; bq[1][1] = r3;
            }
#pragma unroll
            for (int mt = 0; mt < 4; mt++)
#pragma unroll
                for (int nt = 0; nt < 2; nt++)
                    MMA16816(acc[mt][nt], a[mt], bq[nt][0], bq[nt][1]);
        }

        // Epilogue: partial score over this half's 128 cols
        const int b = m0 >> 11;
        const float* dec = g_dec + b * 256;
        float decv[4], vv[4];
#pragma unroll
        for (int nt = 0; nt < 2; nt++)
#pragma unroll
            for (int q = 0; q < 2; q++) {
                const int cloc = n0w + nt * 8 + ((lane & 3) << 1) + q;
                decv[nt * 2 + q] = dec[half * 128 + cloc];
                vv[nt * 2 + q] = vs[cloc];
            }
        float rs[4][2] = {{0.f, 0.f}, {0.f, 0.f}, {0.f, 0.f}, {0.f, 0.f}};
#pragma unroll
        for (int mt = 0; mt < 4; mt++)
#pragma unroll
            for (int nt = 0; nt < 2; nt++)
#pragma unroll
                for (int i = 0; i < 4; i++) {
                    const float f = acc[mt][nt][i] + decv[nt * 2 + (i & 1)];
                    rs[mt][i >> 1] += tanhf(f) * vv[nt * 2 + (i & 1)];
                }
#pragma unroll
        for (int mt = 0; mt < 4; mt++)
#pragma unroll
            for (int j = 0; j < 2; j++) {
                float v = rs[mt][j];
                v += __shfl_xor_sync(0xffffffffu, v, 1);
                v += __shfl_xor_sync(0xffffffffu, v, 2);
                if ((lane & 3) == 0)
                    sred[(mt * 16 + (lane >> 2) + j * 8) * 8 + warp] = v;
            }
        __syncthreads();
        if (tid < 64) {
            float s = 0.f;
#pragma unroll
            for (int w = 0; w < 8; w++) s += sred[tid * 8 + w];
            g_scorep[half * 32768 + m0 + tid] = s;
        }
    }
}

// -------------------- block-wide masked softmax into SMEM (deterministic) ----------
__device__ __forceinline__ void block_softmax(int b, const float* __restrict__ mask,
                                              float* attnAll, float* wred) {
    const int tid = threadIdx.x;
    const int lane = tid & 31, wid = tid >> 5;
    const float* sc0 = g_scorep + b * 2048;
    const float* sc1 = g_scorep + 32768 + b * 2048;
    const float* mk = mask + b * 2048;
    float v[8], m[8];
    float lmax = -1e30f;
#pragma unroll
    for (int i = 0; i < 8; i++) {
        v[i] = sc0[tid + i * 256] + sc1[tid + i * 256];
        m[i] = mk[tid + i * 256];
        lmax = fmaxf(lmax, v[i]);
    }
#pragma unroll
    for (int o = 16; o > 0; o >>= 1) lmax = fmaxf(lmax, __shfl_xor_sync(0xffffffffu, lmax, o));
    if (lane == 0) wred[wid] = lmax;
    __syncthreads();
    float gmax = wred[0];
#pragma unroll
    for (int w = 1; w < 8; w++) gmax = fmaxf(gmax, wred[w]);
    __syncthreads();
    float lsum = 0.f;
#pragma unroll
    for (int i = 0; i < 8; i++) {
        v[i] = expf(v[i] - gmax) * m[i];
        lsum += v[i];
    }
#pragma unroll
    for (int o = 16; o > 0; o >>= 1) lsum += __shfl_xor_sync(0xffffffffu, lsum, o);
    if (lane == 0) wred[wid] = lsum;
    __syncthreads();
    float gsum = 0.f;
#pragma unroll
    for (int w = 0; w < 8; w++) gsum += wred[w];
    const float inv = 1.0f / gsum;
#pragma unroll
    for (int i = 0; i < 8; i++) attnAll[tid + i * 256] = v[i] * inv;
    __syncthreads();
}

// -------------------- K5: fused streamer: softmax + tokp + ct + onehp --------------
// blocks [0,512):    tokp   (n2t, __ldcs); tc==0 blocks write attn_out
// blocks [512,640):  ct     (enc, partly L2-hot from gemm)
// blocks [640,1152): onehp  (graph)
__global__ void __launch_bounds__(256) stream_kernel(const float* __restrict__ n2t,
                                                     const float* __restrict__ enc,
                                                     const float* __restrict__ graph,
                                                     const float* __restrict__ mask,
                                                     float* __restrict__ attn_out) {
    const int bid = blockIdx.x;
    const int tid = threadIdx.x;
    __shared__ float attnAll[2048];
    __shared__ float wred[8];
    __shared__ float4 red[256];

    if (bid < 512) {
        const int b = bid >> 5;
        const int tc = (bid >> 3) & 3;
        const int kc = bid & 7;
        block_softmax(b, mask, attnAll, wred);
        if (tc == 0) attn_out[b * 2048 + kc * 256 + tid] = attnAll[kc * 256 + tid];
        const float* asm_ = attnAll + kc * 256;
        const float4* N4 = reinterpret_cast<const float4*>(n2t) +
                           (size_t)b * 2048 * 1024 + (size_t)kc * 256 * 1024 + tc * 256 + tid;
        float4 acc = make_float4(0.f, 0.f, 0.f, 0.f);
#pragma unroll 8
        for (int k = 0; k < 256; k++) {
            const float a = asm_[k];
            const float4 v = __ldcs(&N4[(size_t)k * 1024]);
            acc.x += a * v.x; acc.y += a * v.y; acc.z += a * v.z; acc.w += a * v.w;
        }
        reinterpret_cast<float4*>(g_tokp)[(kc * 16 + b) * 1024 + tc * 256 + tid] = acc;
    } else if (bid < 640) {
        const int idx = bid - 512;
        const int b = idx >> 3, kc = idx & 7;
        const int rg = tid >> 6;
        const int hc = tid & 63;
        block_softmax(b, mask, attnAll, wred);
        const float* asm_ = attnAll + kc * 256;
        const float4* E4 = reinterpret_cast<const float4*>(enc) +
                           (size_t)(b * 2048 + kc * 256) * 64 + hc;
        float4 acc = make_float4(0.f, 0.f, 0.f, 0.f);
#pragma unroll 8
        for (int k = rg; k < 256; k += 4) {
            const float a = asm_[k];
            const float4 e = E4[(size_t)k * 64];
            acc.x += a * e.x; acc.y += a * e.y; acc.z += a * e.z; acc.w += a * e.w;
        }
        red[tid] = acc;
        __syncthreads();
        if (tid < 64) {
            float4 s0 = red[tid], s1 = red[tid + 64], s2 = red[tid + 128], s3 = red[tid + 192];
            float4 s;
            s.x = (s0.x + s1.x) + (s2.x + s3.x);
            s.y = (s0.y + s1.y) + (s2.y + s3.y);
            s.z = (s0.z + s1.z) + (s2.z + s3.z);
            s.w = (s0.w + s1.w) + (s2.w + s3.w);
            reinterpret_cast<float4*>(g_ctp)[(kc * 16 + b) * 64 + tid] = s;
        }
    } else {
        const int idx = bid - 640;
        const int b = idx >> 5;
        const int mc = (idx >> 4) & 1;
        const int kc = idx & 15;
        block_softmax(b, mask, attnAll, wred);
        const float* asm_ = attnAll + kc * 128;
        const float4* G4 = reinterpret_cast<const float4*>(graph) +
                           (size_t)b * 2048 * 512 + (size_t)kc * 128 * 512 + mc * 256 + tid;
        float4 acc = make_float4(0.f, 0.f, 0.f, 0.f);
#pragma unroll 8
        for (int k = 0; k < 128; k++) {
            const float a = asm_[k];
            const float4 v = G4[(size_t)k * 512];
            acc.x += a * v.x; acc.y += a * v.y; acc.z += a * v.z; acc.w += a * v.w;
        }
        reinterpret_cast<float4*>(g_onehp)[(kc * 16 + b) * 512 + mc * 256 + tid] = acc;
    }
}

// -------------------- K6: two_hop partials (1024 blocks, 64-k chunks) ---------------
__global__ void __launch_bounds__(256) twohp_kernel(const float* __restrict__ graph) {
    const int idx = 1023 - (int)blockIdx.x;
    const int b = idx >> 6;
    const int mc = (idx >> 5) & 1;
    const int kc2 = idx & 31;
    const int tid = threadIdx.x;
    __shared__ float osm[64];
    if (tid < 64) {
        float s = 0.f;
#pragma unroll
        for (int p = 0; p < 16; p++)
            s += g_onehp[(p * 16 + b) * 2048 + kc2 * 64 + tid];
        osm[tid] = s;
    }
    __syncthreads();
    const float4* G4 = reinterpret_cast<const float4*>(graph) +
                       (size_t)b * 2048 * 512 + (size_t)kc2 * 64 * 512 + mc * 256 + tid;
    float4 acc = make_float4(0.f, 0.f, 0.f, 0.f);
#pragma unroll 8
    for (int k = 63; k >= 0; k--) {
        const float a = osm[k];
        const float4 v = __ldcs(&G4[(size_t)k * 512]);
        acc.x += a * v.x; acc.y += a * v.y; acc.z += a * v.z; acc.w += a * v.w;
    }
    reinterpret_cast<float4*>(g_twohp)[(kc2 * 16 + b) * 512 + mc * 256 + tid] = acc;
}

// -------------------- K7: finish (tok reduce+norm, c_t, flow_out) -------------------
__global__ void __launch_bounds__(512) finish_kernel(const float* __restrict__ attn,
                                                     float* __restrict__ ct_out,
                                                     float* __restrict__ tok_out,
                                                     float* __restrict__ flow_out) {
    const int b = blockIdx.x, tid = threadIdx.x;
    float4 v0 = make_float4(0.f, 0.f, 0.f, 0.f);
    float4 v1 = make_float4(0.f, 0.f, 0.f, 0.f);
#pragma unroll
    for (int p = 0; p < 8; p++) {
        const float4 a = reinterpret_cast<const float4*>(g_tokp)[(p * 16 + b) * 1024 + tid * 2];
        const float4 c = reinterpret_cast<const float4*>(g_tokp)[(p * 16 + b) * 1024 + tid * 2 + 1];
        v0.x += a.x; v0.y += a.y; v0.z += a.z; v0.w += a.w;
        v1.x += c.x; v1.y += c.y; v1.z += c.z; v1.w += c.w;
    }
    __shared__ float red[512];
    red[tid] = (v0.x + v0.y + v0.z + v0.w) + (v1.x + v1.y + v1.z + v1.w);
    __syncthreads();
    for (int s = 256; s > 0; s >>= 1) {
        if (tid < s) red[tid] += red[tid + s];
        __syncthreads();
    }
    const float inv = 1.0f / red[0];
    float4 o0, o1;
    o0.x = v0.x * inv; o0.y = v0.y * inv; o0.z = v0.z * inv; o0.w = v0.w * inv;
    o1.x = v1.x * inv; o1.y = v1.y * inv; o1.z = v1.z * inv; o1.w = v1.w * inv;
    reinterpret_cast<float4*>(tok_out)[b * 1024 + tid * 2] = o0;
    reinterpret_cast<float4*>(tok_out)[b * 1024 + tid * 2 + 1] = o1;
    if (tid < 256) {
        float s = 0.f;
#pragma unroll
        for (int kc = 0; kc < 8; kc++) s += g_ctp[(kc * 16 + b) * 256 + tid];
        ct_out[b * 256 + tid] = s;
    }
    {
        float4 two = make_float4(0.f, 0.f, 0.f, 0.f);
        float4 one = make_float4(0.f, 0.f, 0.f, 0.f);
#pragma unroll
        for (int p = 0; p < 32; p++) {
            const float4 t = reinterpret_cast<const float4*>(g_twohp)[(p * 16 + b) * 512 + tid];
            two.x += t.x; two.y += t.y; two.z += t.z; two.w += t.w;
        }
#pragma unroll
        for (int p = 0; p < 16; p++) {
            const float4 o = reinterpret_cast<const float4*>(g_onehp)[(p * 16 + b) * 512 + tid];
            one.x += o.x; one.y += o.y; one.z += o.z; one.w += o.w;
        }
        const float4 a = reinterpret_cast<const float4*>(attn)[b * 512 + tid];
        float4 r;
        r.x = 0.33333f * (a.x + one.x + two.x);
        r.y = 0.33333f * (a.y + one.y + two.y);
        r.z = 0.33333f * (a.z + one.z + two.z);
        r.w = 0.33333f * (a.w + one.w + two.w);
        reinterpret_cast<float4*>(flow_out)[b * 512 + tid] = r;
    }
}

// -------------------- launch --------------------------------------------------------
extern "C" void kernel_launch(void* const* d_in, const int* in_sizes, int n_in,
                              void* d_out, int out_size) {
    const float* s_t_hat = (const float*)d_in[0];   // (16, 512)
    const float* enc     = (const float*)d_in[1];   // (16, 2048, 256)
    const float* n2t     = (const float*)d_in[2];   // (16, 2048, 4096)
    const float* mask    = (const float*)d_in[3];   // (16, 2048)
    const float* graph   = (const float*)d_in[4];   // (16, 2048, 2048)
    // d_in[5] = flow, d_in[6] = W_c_w : dead code in reference, never read
    const float* encw    = (const float*)d_in[7];   // (256, 256)
    const float* decw    = (const float*)d_in[8];   // (512, 256)
    const float* decb    = (const float*)d_in[9];   // (256,)
    const float* vw      = (const float*)d_in[10];  // (256, 1)

    float* out      = (float*)d_out;
    float* ct_out   = out;                    // (16, 256)
    float* attn_out = out + 4096;             // (16, 2048)
    float* tok_out  = out + 4096 + 32768;     // (16, 4096)
    float* flow_out = out + 4096 + 32768 + 65536;  // (16, 2048)

    cudaFuncSetAttribute(gemm_scores_kernel, cudaFuncAttributeMaxDynamicSharedMemorySize,
                         GEMM_SMEM);

    prep_wt_kernel<<<64, 256>>>(encw);
    dec_fea_kernel<<<16, 256>>>(s_t_hat, decw, decb);
    zero_kernel<<<1, 128>>>();
    gemm_scores_kernel<<<296, 256, GEMM_SMEM>>>(enc, vw);
    stream_kernel<<<1152, 256>>>(n2t, enc, graph, mask, attn_out);
    twohp_kernel<<<1024, 256>>>(graph);
    finish_kernel<<<16, 512>>>(attn_out, ct_out, tok_out, flow_out);
}

// round 15
// speedup vs baseline: 1.0337x; 1.0157x over previous
#include <cuda_runtime.h>
#include <cuda_bf16.h>
#include <cstdint>

// Problem constants
#define Bb 16
#define NK 2048
#define TK 4096
#define Hh 256

// -------------------- scratch (device globals; no allocation) --------------------
__device__ __align__(16) float          g_dec[Bb * Hh];          // dec_fea (16,256)
__device__ __align__(16) __nv_bfloat16  g_wt[Hh * Hh];           // enc_proj^T in bf16, [n][k]
__device__ __align__(16) float          g_scorep[2 * Bb * NK];   // score partials (2 n-halves)
__device__ __align__(16) float          g_ctp[8 * Bb * Hh];      // c_t partials (8 k-chunks)
__device__ __align__(16) float          g_tokp[8 * Bb * TK];     // tok partials (8 k-chunks)
__device__ __align__(16) float          g_onehp[16 * Bb * NK];   // one_hop partials (16 k-chunks)
__device__ __align__(16) float          g_twohp[32 * Bb * NK];   // two_hop partials (32 k-chunks)

// -------------------- K1: W transpose -> bf16 [n][k] ------------------------------
__global__ void __launch_bounds__(256) prep_wt_kernel(const float* __restrict__ encw) {
    __shared__ float tile[32][33];
    const int bx = blockIdx.x & 7;        // k tile
    const int by = blockIdx.x >> 3;       // n tile
    const int k0 = bx * 32, n0 = by * 32;
    const int tx = threadIdx.x & 31, ty = threadIdx.x >> 5;
#pragma unroll
    for (int i = 0; i < 32; i += 8)
        tile[ty + i][tx] = encw[(k0 + ty + i) * 256 + n0 + tx];
    __syncthreads();
#pragma unroll
    for (int i = 0; i < 32; i += 8)
        g_wt[(n0 + ty + i) * 256 + k0 + tx] = __float2bfloat16(tile[tx][ty + i]);
}

// -------------------- K2: dec_fea -------------------------------------------------
__global__ void __launch_bounds__(256) dec_fea_kernel(const float* __restrict__ s_t,
                                                      const float* __restrict__ decw,
                                                      const float* __restrict__ bias) {
    const int b = blockIdx.x;
    const int h = threadIdx.x;
    __shared__ float ss[512];
    for (int i = threadIdx.x; i < 512; i += 256) ss[i] = s_t[b * 512 + i];
    __syncthreads();
    float acc = bias[h];
#pragma unroll 8
    for (int j = 0; j < 512; j++) acc += ss[j] * decw[j * 256 + h];
    g_dec[b * 256 + h] = acc;
}

// -------------------- K3: tiny filler (launch spacing, matches champion config) ----
__global__ void zero_kernel() { g_tokp[threadIdx.x] = 0.0f; }   // fully overwritten later

// -------------------- K4: split-N GEMM, 2x4 warp tile (32 rows x 32 cols / warp) ----
// grid=296 (even). half = bid&1. Per ks: 2 A-LDSM + 2 B-LDSM for 16 MMAs
// (vs 5 LDSM / 8 MMAs before) -> 2.5x less shared-pipe pressure per MMA.
#define GEMM_SMEM (128 * 264 * 2 + 64 * 264 * 2 + 64 * 4 * 4 + 128 * 4)

#define LDSM4(r0, r1, r2, r3, addr)                                              \
    asm volatile("ldmatrix.sync.aligned.m8n8.x4.shared.b16 {%0,%1,%2,%3}, [%4];" \
                 : "=r"(r0), "=r"(r1), "=r"(r2), "=r"(r3)                        \
                 : "r"(addr))

#define MMA16816(c, a, b0v, b1v)                                                   \
    asm volatile(                                                                  \
        "mma.sync.aligned.m16n8k16.row.col.f32.bf16.bf16.f32 "                     \
        "{%0,%1,%2,%3},{%4,%5,%6,%7},{%8,%9},{%0,%1,%2,%3};"                       \
        : "+f"(c[0]), "+f"(c[1]), "+f"(c[2]), "+f"(c[3])                           \
        : "r"(a[0]), "r"(a[1]), "r"(a[2]), "r"(a[3]), "r"(b0v), "r"(b1v))

__global__ void __launch_bounds__(256, 2) gemm_scores_kernel(const float* __restrict__ enc,
                                                             const float* __restrict__ vw) {
    extern __shared__ char smraw[];
    __nv_bfloat16* Ws = reinterpret_cast<__nv_bfloat16*>(smraw);   // [128][264]
    __nv_bfloat16* As = Ws + 128 * 264;                            // [64][264]
    float* sred = reinterpret_cast<float*>(As + 64 * 264);         // [64][4]
    float* vs = sred + 64 * 4;                                     // [128]

    const int tid = threadIdx.x;
    const int warp = tid >> 5;      // 0..7
    const int lane = tid & 31;
    const int half = blockIdx.x & 1;
    const int mw = warp >> 2;       // 0..1  (M group: 32 rows)
    const int nw = warp & 3;        // 0..3  (N group: 32 cols within half)

    // Stage this block's W^T half once
    {
        const uint4* src = reinterpret_cast<const uint4*>(g_wt + half * 128 * 256);
        for (int i = tid; i < 4096; i += 256) {
            const int n = i >> 5, c = i & 31;
            *reinterpret_cast<uint4*>(Ws + n * 264 + c * 8) = src[i];
        }
    }
    if (tid < 128) vs[tid] = vw[half * 128 + tid];

    const unsigned AsB = (unsigned)__cvta_generic_to_shared(As);
    const unsigned WsB = (unsigned)__cvta_generic_to_shared(Ws);
    const int n0w = nw * 32;        // 32 N-cols per warp (within half)

    unsigned a_off[2];
#pragma unroll
    for (int mt = 0; mt < 2; mt++)
        a_off[mt] = AsB + 2u * ((unsigned)((mw * 32 + mt * 16 + (lane & 15)) * 264 +
                                           ((lane >> 4) << 3)));
    unsigned b_off[2];
#pragma unroll
    for (int nt2 = 0; nt2 < 2; nt2++)
        b_off[nt2] = WsB + 2u * ((unsigned)((n0w + nt2 * 16 + ((lane >> 4) << 3) + (lane & 7)) * 264 +
                                            (((lane >> 3) & 1) << 3)));

    const float4* srcBase = reinterpret_cast<const float4*>(enc);

    for (int t = blockIdx.x; t < 1024; t += gridDim.x) {
        const int m0 = (t >> 1) * 64;
        __syncthreads();   // As free, previous sred reads done
        // Stage + convert A tile (64 x 256), fp32 -> bf16 (hidden by co-resident block)
        {
            const float4* s = srcBase + (size_t)(t >> 1) * 4096;
#pragma unroll
            for (int j = 0; j < 16; j++) {
                const int i = tid + j * 256;
                const int r = i >> 6, c = i & 63;
                const float4 f = s[i];
                __nv_bfloat162 p0 = __floats2bfloat162_rn(f.x, f.y);
                __nv_bfloat162 p1 = __floats2bfloat162_rn(f.z, f.w);
                uint2 u;
                u.x = *reinterpret_cast<const unsigned*>(&p0);
                u.y = *reinterpret_cast<const unsigned*>(&p1);
                *reinterpret_cast<uint2*>(As + r * 264 + c * 4) = u;
            }
        }
        __syncthreads();   // As ready

        float acc[2][4][4];
#pragma unroll
        for (int mt = 0; mt < 2; mt++)
#pragma unroll
            for (int nt = 0; nt < 4; nt++)
#pragma unroll
                for (int i = 0; i < 4; i++) acc[mt][nt][i] = 0.0f;

#pragma unroll
        for (int ks = 0; ks < 16; ks++) {
            const unsigned k0b = 2u * (unsigned)(ks * 16);
            unsigned a[2][4];
            unsigned bq[4][2];
#pragma unroll
            for (int mt = 0; mt < 2; mt++)
                LDSM4(a[mt][0], a[mt][1], a[mt][2], a[mt][3], a_off[mt] + k0b);
#pragma unroll
            for (int nt2 = 0; nt2 < 2; nt2++) {
                unsigned r0, r1, r2, r3;
                LDSM4(r0, r1, r2, r3, b_off[nt2] + k0b);
                bq[nt2 * 2][0] = r0;     bq[nt2 * 2][1] = r1;
                bq[nt2 * 2 + 1][0] = r2; bq[nt2 * 2 + 1][1] = r3;
            }
#pragma unroll
            for (int mt = 0; mt < 2; mt++)
#pragma unroll
                for (int nt = 0; nt < 4; nt++)
                    MMA16816(acc[mt][nt], a[mt], bq[nt][0], bq[nt][1]);
        }

        // Epilogue: partial score over this warp's 32 rows x 32 cols
        const int b = m0 >> 11;
        const float* dec = g_dec + b * 256;
        float decv[8], vv[8];
#pragma unroll
        for (int nt = 0; nt < 4; nt++)
#pragma unroll
            for (int q = 0; q < 2; q++) {
                const int cloc = n0w + nt * 8 + ((lane & 3) << 1) + q;
                decv[nt * 2 + q] = dec[half * 128 + cloc];
                vv[nt * 2 + q] = vs[cloc];
            }
        float rs[2][2] = {{0.f, 0.f}, {0.f, 0.f}};
#pragma unroll
        for (int mt = 0; mt < 2; mt++)
#pragma unroll
            for (int nt = 0; nt < 4; nt++)
#pragma unroll
                for (int i = 0; i < 4; i++) {
                    const float f = acc[mt][nt][i] + decv[nt * 2 + (i & 1)];
                    rs[mt][i >> 1] += tanhf(f) * vv[nt * 2 + (i & 1)];
                }
#pragma unroll
        for (int mt = 0; mt < 2; mt++)
#pragma unroll
            for (int j = 0; j < 2; j++) {
                float v = rs[mt][j];
                v += __shfl_xor_sync(0xffffffffu, v, 1);
                v += __shfl_xor_sync(0xffffffffu, v, 2);
                if ((lane & 3) == 0)
                    sred[(mw * 32 + mt * 16 + (lane >> 2) + j * 8) * 4 + nw] = v;
            }
        __syncthreads();
        if (tid < 64) {
            float s = 0.f;
#pragma unroll
            for (int w = 0; w < 4; w++) s += sred[tid * 4 + w];
            g_scorep[half * 32768 + m0 + tid] = s;
        }
    }
}

// -------------------- block-wide masked softmax into SMEM (deterministic) ----------
__device__ __forceinline__ void block_softmax(int b, const float* __restrict__ mask,
                                              float* attnAll, float* wred) {
    const int tid = threadIdx.x;
    const int lane = tid & 31, wid = tid >> 5;
    const float* sc0 = g_scorep + b * 2048;
    const float* sc1 = g_scorep + 32768 + b * 2048;
    const float* mk = mask + b * 2048;
    float v[8], m[8];
    float lmax = -1e30f;
#pragma unroll
    for (int i = 0; i < 8; i++) {
        v[i] = sc0[tid + i * 256] + sc1[tid + i * 256];
        m[i] = mk[tid + i * 256];
        lmax = fmaxf(lmax, v[i]);
    }
#pragma unroll
    for (int o = 16; o > 0; o >>= 1) lmax = fmaxf(lmax, __shfl_xor_sync(0xffffffffu, lmax, o));
    if (lane == 0) wred[wid] = lmax;
    __syncthreads();
    float gmax = wred[0];
#pragma unroll
    for (int w = 1; w < 8; w++) gmax = fmaxf(gmax, wred[w]);
    __syncthreads();
    float lsum = 0.f;
#pragma unroll
    for (int i = 0; i < 8; i++) {
        v[i] = expf(v[i] - gmax) * m[i];
        lsum += v[i];
    }
#pragma unroll
    for (int o = 16; o > 0; o >>= 1) lsum += __shfl_xor_sync(0xffffffffu, lsum, o);
    if (lane == 0) wred[wid] = lsum;
    __syncthreads();
    float gsum = 0.f;
#pragma unroll
    for (int w = 0; w < 8; w++) gsum += wred[w];
    const float inv = 1.0f / gsum;
#pragma unroll
    for (int i = 0; i < 8; i++) attnAll[tid + i * 256] = v[i] * inv;
    __syncthreads();
}

// -------------------- K5: fused streamer: softmax + tokp + ct + onehp --------------
// blocks [0,512):    tokp   (n2t, __ldcs); tc==0 blocks write attn_out
// blocks [512,640):  ct     (enc, partly L2-hot from gemm)
// blocks [640,1152): onehp  (graph)
__global__ void __launch_bounds__(256) stream_kernel(const float* __restrict__ n2t,
                                                     const float* __restrict__ enc,
                                                     const float* __restrict__ graph,
                                                     const float* __restrict__ mask,
                                                     float* __restrict__ attn_out) {
    const int bid = blockIdx.x;
    const int tid = threadIdx.x;
    __shared__ float attnAll[2048];
    __shared__ float wred[8];
    __shared__ float4 red[256];

    if (bid < 512) {
        const int b = bid >> 5;
        const int tc = (bid >> 3) & 3;
        const int kc = bid & 7;
        block_softmax(b, mask, attnAll, wred);
        if (tc == 0) attn_out[b * 2048 + kc * 256 + tid] = attnAll[kc * 256 + tid];
        const float* asm_ = attnAll + kc * 256;
        const float4* N4 = reinterpret_cast<const float4*>(n2t) +
                           (size_t)b * 2048 * 1024 + (size_t)kc * 256 * 1024 + tc * 256 + tid;
        float4 acc = make_float4(0.f, 0.f, 0.f, 0.f);
#pragma unroll 8
        for (int k = 0; k < 256; k++) {
            const float a = asm_[k];
            const float4 v = __ldcs(&N4[(size_t)k * 1024]);
            acc.x += a * v.x; acc.y += a * v.y; acc.z += a * v.z; acc.w += a * v.w;
        }
        reinterpret_cast<float4*>(g_tokp)[(kc * 16 + b) * 1024 + tc * 256 + tid] = acc;
    } else if (bid < 640) {
        const int idx = bid - 512;
        const int b = idx >> 3, kc = idx & 7;
        const int rg = tid >> 6;
        const int hc = tid & 63;
        block_softmax(b, mask, attnAll, wred);
        const float* asm_ = attnAll + kc * 256;
        const float4* E4 = reinterpret_cast<const float4*>(enc) +
                           (size_t)(b * 2048 + kc * 256) * 64 + hc;
        float4 acc = make_float4(0.f, 0.f, 0.f, 0.f);
#pragma unroll 8
        for (int k = rg; k < 256; k += 4) {
            const float a = asm_[k];
            const float4 e = E4[(size_t)k * 64];
            acc.x += a * e.x; acc.y += a * e.y; acc.z += a * e.z; acc.w += a * e.w;
        }
        red[tid] = acc;
        __syncthreads();
        if (tid < 64) {
            float4 s0 = red[tid], s1 = red[tid + 64], s2 = red[tid + 128], s3 = red[tid + 192];
            float4 s;
            s.x = (s0.x + s1.x) + (s2.x + s3.x);
            s.y = (s0.y + s1.y) + (s2.y + s3.y);
            s.z = (s0.z + s1.z) + (s2.z + s3.z);
            s.w = (s0.w + s1.w) + (s2.w + s3.w);
            reinterpret_cast<float4*>(g_ctp)[(kc * 16 + b) * 64 + tid] = s;
        }
    } else {
        const int idx = bid - 640;
        const int b = idx >> 5;
        const int mc = (idx >> 4) & 1;
        const int kc = idx & 15;
        block_softmax(b, mask, attnAll, wred);
        const float* asm_ = attnAll + kc * 128;
        const float4* G4 = reinterpret_cast<const float4*>(graph) +
                           (size_t)b * 2048 * 512 + (size_t)kc * 128 * 512 + mc * 256 + tid;
        float4 acc = make_float4(0.f, 0.f, 0.f, 0.f);
#pragma unroll 8
        for (int k = 0; k < 128; k++) {
            const float a = asm_[k];
            const float4 v = G4[(size_t)k * 512];
            acc.x += a * v.x; acc.y += a * v.y; acc.z += a * v.z; acc.w += a * v.w;
        }
        reinterpret_cast<float4*>(g_onehp)[(kc * 16 + b) * 512 + mc * 256 + tid] = acc;
    }
}

// -------------------- K6: two_hop partials (1024 blocks, 64-k chunks) ---------------
__global__ void __launch_bounds__(256) twohp_kernel(const float* __restrict__ graph) {
    const int idx = 1023 - (int)blockIdx.x;
    const int b = idx >> 6;
    const int mc = (idx >> 5) & 1;
    const int kc2 = idx & 31;
    const int tid = threadIdx.x;
    __shared__ float osm[64];
    if (tid < 64) {
        float s = 0.f;
#pragma unroll
        for (int p = 0; p < 16; p++)
            s += g_onehp[(p * 16 + b) * 2048 + kc2 * 64 + tid];
        osm[tid] = s;
    }
    __syncthreads();
    const float4* G4 = reinterpret_cast<const float4*>(graph) +
                       (size_t)b * 2048 * 512 + (size_t)kc2 * 64 * 512 + mc * 256 + tid;
    float4 acc = make_float4(0.f, 0.f, 0.f, 0.f);
#pragma unroll 8
    for (int k = 63; k >= 0; k--) {
        const float a = osm[k];
        const float4 v = __ldcs(&G4[(size_t)k * 512]);
        acc.x += a * v.x; acc.y += a * v.y; acc.z += a * v.z; acc.w += a * v.w;
    }
    reinterpret_cast<float4*>(g_twohp)[(kc2 * 16 + b) * 512 + mc * 256 + tid] = acc;
}

// -------------------- K7: finish (tok reduce+norm, c_t, flow_out) -------------------
__global__ void __launch_bounds__(512) finish_kernel(const float* __restrict__ attn,
                                                     float* __restrict__ ct_out,
                                                     float* __restrict__ tok_out,
                                                     float* __restrict__ flow_out) {
    const int b = blockIdx.x, tid = threadIdx.x;
    float4 v0 = make_float4(0.f, 0.f, 0.f, 0.f);
    float4 v1 = make_float4(0.f, 0.f, 0.f, 0.f);
#pragma unroll
    for (int p = 0; p < 8; p++) {
        const float4 a = reinterpret_cast<const float4*>(g_tokp)[(p * 16 + b) * 1024 + tid * 2];
        const float4 c = reinterpret_cast<const float4*>(g_tokp)[(p * 16 + b) * 1024 + tid * 2 + 1];
        v0.x += a.x; v0.y += a.y; v0.z += a.z; v0.w += a.w;
        v1.x += c.x; v1.y += c.y; v1.z += c.z; v1.w += c.w;
    }
    __shared__ float red[512];
    red[tid] = (v0.x + v0.y + v0.z + v0.w) + (v1.x + v1.y + v1.z + v1.w);
    __syncthreads();
    for (int s = 256; s > 0; s >>= 1) {
        if (tid < s) red[tid] += red[tid + s];
        __syncthreads();
    }
    const float inv = 1.0f / red[0];
    float4 o0, o1;
    o0.x = v0.x * inv; o0.y = v0.y * inv; o0.z = v0.z * inv; o0.w = v0.w * inv;
    o1.x = v1.x * inv; o1.y = v1.y * inv; o1.z = v1.z * inv; o1.w = v1.w * inv;
    reinterpret_cast<float4*>(tok_out)[b * 1024 + tid * 2] = o0;
    reinterpret_cast<float4*>(tok_out)[b * 1024 + tid * 2 + 1] = o1;
    if (tid < 256) {
        float s = 0.f;
#pragma unroll
        for (int kc = 0; kc < 8; kc++) s += g_ctp[(kc * 16 + b) * 256 + tid];
        ct_out[b * 256 + tid] = s;
    }
    {
        float4 two = make_float4(0.f, 0.f, 0.f, 0.f);
        float4 one = make_float4(0.f, 0.f, 0.f, 0.f);
#pragma unroll
        for (int p = 0; p < 32; p++) {
            const float4 t = reinterpret_cast<const float4*>(g_twohp)[(p * 16 + b) * 512 + tid];
            two.x += t.x; two.y += t.y; two.z += t.z; two.w += t.w;
        }
#pragma unroll
        for (int p = 0; p < 16; p++) {
            const float4 o = reinterpret_cast<const float4*>(g_onehp)[(p * 16 + b) * 512 + tid];
            one.x += o.x; one.y += o.y; one.z += o.z; one.w += o.w;
        }
        const float4 a = reinterpret_cast<const float4*>(attn)[b * 512 + tid];
        float4 r;
        r.x = 0.33333f * (a.x + one.x + two.x);
        r.y = 0.33333f * (a.y + one.y + two.y);
        r.z = 0.33333f * (a.z + one.z + two.z);
        r.w = 0.33333f * (a.w + one.w + two.w);
        reinterpret_cast<float4*>(flow_out)[b * 512 + tid] = r;
    }
}

// -------------------- launch --------------------------------------------------------
extern "C" void kernel_launch(void* const* d_in, const int* in_sizes, int n_in,
                              void* d_out, int out_size) {
    const float* s_t_hat = (const float*)d_in[0];   // (16, 512)
    const float* enc     = (const float*)d_in[1];   // (16, 2048, 256)
    const float* n2t     = (const float*)d_in[2];   // (16, 2048, 4096)
    const float* mask    = (const float*)d_in[3];   // (16, 2048)
    const float* graph   = (const float*)d_in[4];   // (16, 2048, 2048)
    // d_in[5] = flow, d_in[6] = W_c_w : dead code in reference, never read
    const float* encw    = (const float*)d_in[7];   // (256, 256)
    const float* decw    = (const float*)d_in[8];   // (512, 256)
    const float* decb    = (const float*)d_in[9];   // (256,)
    const float* vw      = (const float*)d_in[10];  // (256, 1)

    float* out      = (float*)d_out;
    float* ct_out   = out;                    // (16, 256)
    float* attn_out = out + 4096;             // (16, 2048)
    float* tok_out  = out + 4096 + 32768;     // (16, 4096)
    float* flow_out = out + 4096 + 32768 + 65536;  // (16, 2048)

    cudaFuncSetAttribute(gemm_scores_kernel, cudaFuncAttributeMaxDynamicSharedMemorySize,
                         GEMM_SMEM);

    prep_wt_kernel<<<64, 256>>>(encw);
    dec_fea_kernel<<<16, 256>>>(s_t_hat, decw, decb);
    zero_kernel<<<1, 128>>>();
    gemm_scores_kernel<<<296, 256, GEMM_SMEM>>>(enc, vw);   // 4th launch -> ncu target
    stream_kernel<<<1152, 256>>>(n2t, enc, graph, mask, attn_out);
    twohp_kernel<<<1024, 256>>>(graph);
    finish_kernel<<<16, 512>>>(attn_out, ct_out, tok_out, flow_out);
}